// round 12
// baseline (speedup 1.0000x reference)
#include <cuda_runtime.h>
#include <cuda_bf16.h>
#include <cstdint>

// ---------------- problem constants ----------------
#define B_   32
#define LS_  256
#define LL_  256
#define L_   512
#define D_   2048
#define H_   16
#define DH_  128
#define T_   1000
#define TAU_ 0.07f
#define SCALE_ 0.08838834764831845f

#define NEL  33554432L   // B*L*D

// ---------------- scratch buffers (static, no allocation) ----------------
__device__ __nv_bfloat16 d_xtb[NEL];            // x_t bf16 [B,L,D]
__device__ __nv_bfloat16 d_wt[4L*2048*2048];    // WqT,WkT,WvT,WoT bf16 [N,K]
__device__ __nv_bfloat16 d_qb[NEL];             // Q bf16
__device__ __nv_bfloat16 d_kb[NEL];             // K bf16
__device__ __nv_bfloat16 d_vb[NEL];             // V bf16
__device__ __nv_bfloat16 d_ob[NEL];             // attn out bf16
__device__ float d_xT[NEL];                     // x_start^T [D,B,L] fp32
__device__ double g_acc[4];

// ---------------- reduction helper (supports up to 16 warps) ----------------
__device__ __forceinline__ double blockReduceSumD(double v) {
    __shared__ double sh[16];
    #pragma unroll
    for (int o = 16; o > 0; o >>= 1) v += __shfl_down_sync(0xffffffffu, v, o);
    int lane = threadIdx.x & 31, w = threadIdx.x >> 5;
    if (lane == 0) sh[w] = v;
    __syncthreads();
    if (w == 0) {
        v = (lane < (int)(blockDim.x >> 5)) ? sh[lane] : 0.0;
        #pragma unroll
        for (int o = 8; o > 0; o >>= 1) v += __shfl_down_sync(0xffffffffu, v, o);
    }
    return v;
}

// ---------------- mma helpers ----------------
__device__ __forceinline__ void mma16816(float* c, const uint32_t* a, const uint32_t* b) {
    asm volatile(
        "mma.sync.aligned.m16n8k16.row.col.f32.bf16.bf16.f32 "
        "{%0,%1,%2,%3}, {%4,%5,%6,%7}, {%8,%9}, {%0,%1,%2,%3};"
        : "+f"(c[0]), "+f"(c[1]), "+f"(c[2]), "+f"(c[3])
        : "r"(a[0]), "r"(a[1]), "r"(a[2]), "r"(a[3]), "r"(b[0]), "r"(b[1]));
}
__device__ __forceinline__ void ldsm4(uint32_t* f, uint32_t addr) {
    asm volatile("ldmatrix.sync.aligned.m8n8.x4.shared.b16 {%0,%1,%2,%3}, [%4];"
                 : "=r"(f[0]), "=r"(f[1]), "=r"(f[2]), "=r"(f[3]) : "r"(addr));
}
__device__ __forceinline__ void ldsm4t(uint32_t* f, uint32_t addr) {
    asm volatile("ldmatrix.sync.aligned.m8n8.x4.trans.shared.b16 {%0,%1,%2,%3}, [%4];"
                 : "=r"(f[0]), "=r"(f[1]), "=r"(f[2]), "=r"(f[3]) : "r"(addr));
}

// ---------------- batched bf16 MMA GEMM ----------------
// C = alpha * A[M,K] @ B[N,K]^T. 256x128 CTA tile, 32x64 warp tile
// (8 M-warps x 2 N-warps = 16 warps = 512 threads), BK=64, 3-stage cp.async,
// one sync per k-step, 1 CTA/SM (same 16 warps/SM as proven config).
// outMode: 1=bf16 store, 2=fused MSE vs concat(eseq,elab), 3=QKV split.
#define SROWK 144   // 128B data + 16B pad
#define G_BM 256
#define G_BN 128
#define G_STAGES 3
#define G_STAGE_BYTES ((G_BM + G_BN) * SROWK)   // 55296
#define SMEM_G (G_STAGES * G_STAGE_BYTES)       // 165888

__global__ __launch_bounds__(512, 1) void mma_gemm(
    const __nv_bfloat16* __restrict__ A, int lda,
    const __nv_bfloat16* __restrict__ Bm, int ldb,
    void* __restrict__ Cv, int ldc,
    int K, float alpha, int outMode,
    const float* __restrict__ xseq, const float* __restrict__ xlab)
{
    extern __shared__ __align__(16) char dsm[];
    uint32_t sbase = (uint32_t)__cvta_generic_to_shared(dsm);

    int tid = threadIdx.x, lane = tid & 31, wid = tid >> 5;
    int m0 = blockIdx.y * G_BM, n0 = blockIdx.x * G_BN;
    int wm = wid & 7, wn = wid >> 3;   // 8 M-warps x 2 N-warps

    const __nv_bfloat16* Ag = A + (long)m0 * lda;
    const __nv_bfloat16* Bg = Bm + (long)n0 * ldb;

    float acc[2][8][4];
    #pragma unroll
    for (int i = 0; i < 2; i++)
        #pragma unroll
        for (int j = 0; j < 8; j++)
            #pragma unroll
            for (int q = 0; q < 4; q++) acc[i][j][q] = 0.f;

    auto load_tile = [&](int sidx, int buf) {
        const __nv_bfloat16* Ab = Ag + (long)sidx * 64;
        const __nv_bfloat16* Bb = Bg + (long)sidx * 64;
        uint32_t stA = sbase + buf * G_STAGE_BYTES;
        uint32_t stB = stA + G_BM * SROWK;
        // A: 256 rows x 8 chunks = 2048 -> 4/thread
        #pragma unroll
        for (int i = 0; i < 4; i++) {
            int ch = i * 512 + tid;
            int r = ch >> 3, c = ch & 7;
            const void* ga = Ab + (long)r * lda + c * 8;
            asm volatile("cp.async.cg.shared.global [%0], [%1], 16;"
                         :: "r"(stA + (uint32_t)(r * SROWK + c * 16)), "l"(ga));
        }
        // B: 128 rows x 8 chunks = 1024 -> 2/thread
        #pragma unroll
        for (int i = 0; i < 2; i++) {
            int ch = i * 512 + tid;
            int r = ch >> 3, c = ch & 7;
            const void* gb = Bb + (long)r * ldb + c * 8;
            asm volatile("cp.async.cg.shared.global [%0], [%1], 16;"
                         :: "r"(stB + (uint32_t)(r * SROWK + c * 16)), "l"(gb));
        }
    };

    int nt = K >> 6;
    #pragma unroll
    for (int i = 0; i < G_STAGES - 1; i++) {
        if (i < nt) load_tile(i, i);
        asm volatile("cp.async.commit_group;" ::: "memory");
    }

    for (int s = 0; s < nt; s++) {
        asm volatile("cp.async.wait_group %0;" :: "n"(G_STAGES - 2) : "memory");
        __syncthreads();
        int pf = s + G_STAGES - 1;
        if (pf < nt) load_tile(pf, pf % G_STAGES);
        asm volatile("cp.async.commit_group;" ::: "memory");

        uint32_t baseA = sbase + (s % G_STAGES) * G_STAGE_BYTES;
        uint32_t baseB = baseA + G_BM * SROWK;
        #pragma unroll
        for (int kk = 0; kk < 4; kk++) {
            uint32_t af[2][4];
            #pragma unroll
            for (int mi = 0; mi < 2; mi++) {
                int row = (wm << 5) + (mi << 4) + (lane & 15);
                uint32_t ad = baseA + (uint32_t)(row * SROWK + (kk << 5) + ((lane >> 4) << 4));
                ldsm4(af[mi], ad);
            }
            uint32_t bf[4][4];
            #pragma unroll
            for (int g = 0; g < 4; g++) {
                int nrow = (wn << 6) + (g << 4) + ((lane >> 4) << 3) + (lane & 7);
                uint32_t bd = baseB + (uint32_t)(nrow * SROWK + (kk << 5) + (((lane >> 3) & 1) << 4));
                ldsm4(bf[g], bd);
            }
            #pragma unroll
            for (int mi = 0; mi < 2; mi++)
                #pragma unroll
                for (int ni = 0; ni < 8; ni++)
                    mma16816(acc[mi][ni], af[mi], &bf[ni >> 1][(ni & 1) * 2]);
        }
    }

    // epilogue
    int tg = lane >> 2, tc = lane & 3;
    if (outMode == 2) {
        float lsum = 0.f;
        #pragma unroll
        for (int mi = 0; mi < 2; mi++) {
            #pragma unroll
            for (int ni = 0; ni < 8; ni++) {
                int row = m0 + (wm << 5) + (mi << 4) + tg;
                int col = n0 + (wn << 6) + (ni << 3) + tc * 2;
                float* a4 = acc[mi][ni];
                #pragma unroll
                for (int h = 0; h < 2; h++) {
                    int r = row + h * 8;
                    int b = r >> 9, l = r & 511;
                    const float* xp = (l < LS_)
                        ? (xseq + ((long)b * LS_ + l) * D_ + col)
                        : (xlab + ((long)b * LL_ + (l - LS_)) * D_ + col);
                    float2 x2 = *(const float2*)xp;
                    float d0 = x2.x - a4[2 * h];
                    float d1 = x2.y - a4[2 * h + 1];
                    lsum += d0 * d0 + d1 * d1;
                }
            }
        }
        double bs = blockReduceSumD((double)lsum);
        if (tid == 0) atomicAdd(&g_acc[1], bs);
        return;
    }
    __nv_bfloat16* C;
    int nb = n0;
    if (outMode == 3) {
        int which = n0 >> 11;
        C = (which == 0) ? d_qb : ((which == 1) ? d_kb : d_vb);
        nb = n0 & 2047;
    } else {
        C = (__nv_bfloat16*)Cv;
    }
    #pragma unroll
    for (int mi = 0; mi < 2; mi++) {
        #pragma unroll
        for (int ni = 0; ni < 8; ni++) {
            int row = m0 + (wm << 5) + (mi << 4) + tg;
            int col = nb + (wn << 6) + (ni << 3) + tc * 2;
            float* a4 = acc[mi][ni];
            __nv_bfloat162 p0 = __floats2bfloat162_rn(a4[0] * alpha, a4[1] * alpha);
            __nv_bfloat162 p1 = __floats2bfloat162_rn(a4[2] * alpha, a4[3] * alpha);
            *(__nv_bfloat162*)(C + (long)row * ldc + col) = p0;
            *(__nv_bfloat162*)(C + (long)(row + 8) * ldc + col) = p1;
        }
    }
}

// ---------------- fully fused attention: S = QK^T -> softmax -> O = P V ----------------
#define ATTN_SMEM 229376

__global__ __launch_bounds__(256, 1) void attn_fused() {
    extern __shared__ __align__(16) char dsm[];
    uint32_t base = (uint32_t)__cvta_generic_to_shared(dsm);
    uint32_t pB = base;
    uint32_t kvB = base + 131072;
    uint32_t qB = base + 196608;

    int tid = threadIdx.x, lane = tid & 31, wid = tid >> 5;
    int z = blockIdx.y, m0 = blockIdx.x << 7;
    int b = z >> 4, h = z & 15;
    const __nv_bfloat16* Qg = d_qb + ((long)b * 512 + m0) * 2048 + h * 128;
    const __nv_bfloat16* Kg = d_kb + (long)b * 512 * 2048 + h * 128;
    const __nv_bfloat16* Vg = d_vb + (long)b * 512 * 2048 + h * 128;
    int wm = wid & 3, wn = wid >> 2;

    auto ld128 = [&](uint32_t dst, const __nv_bfloat16* src) {
        #pragma unroll
        for (int i = 0; i < 8; i++) {
            int id = i * 256 + tid;
            int r = id >> 4, u = id & 15;
            const void* g = src + (long)r * 2048 + u * 8;
            uint32_t d = dst + (uint32_t)(r * 256 + ((u ^ (r & 7)) << 4));
            asm volatile("cp.async.cg.shared.global [%0], [%1], 16;" :: "r"(d), "l"(g));
        }
    };

    ld128(qB, Qg);
    asm volatile("cp.async.commit_group;" ::: "memory");
    ld128(kvB, Kg);
    asm volatile("cp.async.commit_group;" ::: "memory");
    ld128(kvB + 32768, Kg + 128L * 2048);
    asm volatile("cp.async.commit_group;" ::: "memory");

    // ---- phase 1: S chunks -> P (bf16, scaled) ----
    for (int c = 0; c < 4; c++) {
        asm volatile("cp.async.wait_group 1;" ::: "memory");
        __syncthreads();
        uint32_t kvb = kvB + (c & 1) * 32768;
        float acc[2][8][4];
        #pragma unroll
        for (int i = 0; i < 2; i++)
            #pragma unroll
            for (int j = 0; j < 8; j++)
                #pragma unroll
                for (int q = 0; q < 4; q++) acc[i][j][q] = 0.f;
        #pragma unroll
        for (int k8 = 0; k8 < 8; k8++) {
            uint32_t af[2][4];
            #pragma unroll
            for (int mi = 0; mi < 2; mi++) {
                int row = (wm << 5) + (mi << 4) + (lane & 15);
                int u = (k8 << 1) + (lane >> 4);
                ldsm4(af[mi], qB + (uint32_t)(row * 256 + ((u ^ (row & 7)) << 4)));
            }
            uint32_t bf[4][4];
            #pragma unroll
            for (int g = 0; g < 4; g++) {
                int nrow = (wn << 6) + (g << 4) + ((lane >> 4) << 3) + (lane & 7);
                int u = (k8 << 1) + ((lane >> 3) & 1);
                ldsm4(bf[g], kvb + (uint32_t)(nrow * 256 + ((u ^ (nrow & 7)) << 4)));
            }
            #pragma unroll
            for (int mi = 0; mi < 2; mi++)
                #pragma unroll
                for (int ni = 0; ni < 8; ni++)
                    mma16816(acc[mi][ni], af[mi], &bf[ni >> 1][(ni & 1) * 2]);
        }
        int tg = lane >> 2, tc = lane & 3;
        #pragma unroll
        for (int mi = 0; mi < 2; mi++) {
            #pragma unroll
            for (int ni = 0; ni < 8; ni++) {
                int row = (wm << 5) + (mi << 4) + tg;
                int ub = (c << 4) + (wn << 3) + ni;
                float* a4 = acc[mi][ni];
                #pragma unroll
                for (int h2 = 0; h2 < 2; h2++) {
                    int r2 = row + h2 * 8;
                    uint32_t off = (uint32_t)(r2 * 1024 + ((ub ^ (r2 & 7)) << 4) + tc * 4);
                    *(__nv_bfloat162*)(dsm + off) = __floats2bfloat162_rn(
                        a4[2 * h2] * SCALE_, a4[2 * h2 + 1] * SCALE_);
                }
            }
        }
        __syncthreads();
        if (c < 2)       ld128(kvB + (c & 1) * 32768, Kg + (long)(c + 2) * 128 * 2048);
        else if (c == 2) ld128(kvB, Vg);
        else             ld128(kvB + 32768, Vg + 128L * 2048);
        asm volatile("cp.async.commit_group;" ::: "memory");
    }

    // ---- softmax in place on P ----
    for (int rr = 0; rr < 16; rr++) {
        int row = wid * 16 + rr;
        int x = row & 7;
        uint32_t a0 = (uint32_t)(row * 1024 + ((lane ^ x) << 4));
        uint32_t a1 = (uint32_t)(row * 1024 + (((lane + 32) ^ x) << 4));
        uint4 u0 = *(uint4*)(dsm + a0);
        uint4 u1 = *(uint4*)(dsm + a1);
        float v[16];
        const uint32_t* w0 = (const uint32_t*)&u0;
        const uint32_t* w1 = (const uint32_t*)&u1;
        #pragma unroll
        for (int j = 0; j < 4; j++) {
            __nv_bfloat162 h0 = *(__nv_bfloat162*)&w0[j];
            __nv_bfloat162 h1 = *(__nv_bfloat162*)&w1[j];
            v[2 * j]     = __bfloat162float(h0.x);
            v[2 * j + 1] = __bfloat162float(h0.y);
            v[8 + 2 * j] = __bfloat162float(h1.x);
            v[9 + 2 * j] = __bfloat162float(h1.y);
        }
        float m = v[0];
        #pragma unroll
        for (int j = 1; j < 16; j++) m = fmaxf(m, v[j]);
        #pragma unroll
        for (int o = 16; o > 0; o >>= 1) m = fmaxf(m, __shfl_xor_sync(0xffffffffu, m, o));
        float s = 0.f;
        #pragma unroll
        for (int j = 0; j < 16; j++) { v[j] = __expf(v[j] - m); s += v[j]; }
        #pragma unroll
        for (int o = 16; o > 0; o >>= 1) s += __shfl_xor_sync(0xffffffffu, s, o);
        float inv = 1.0f / s;
        uint32_t pk[8];
        #pragma unroll
        for (int j = 0; j < 4; j++) {
            __nv_bfloat162 pa = __floats2bfloat162_rn(v[2 * j] * inv, v[2 * j + 1] * inv);
            __nv_bfloat162 pb = __floats2bfloat162_rn(v[8 + 2 * j] * inv, v[9 + 2 * j] * inv);
            pk[j] = *(uint32_t*)&pa;
            pk[4 + j] = *(uint32_t*)&pb;
        }
        *(uint4*)(dsm + a0) = make_uint4(pk[0], pk[1], pk[2], pk[3]);
        *(uint4*)(dsm + a1) = make_uint4(pk[4], pk[5], pk[6], pk[7]);
    }

    // ---- phase 2: O = P @ V ----
    float acc[2][8][4];
    #pragma unroll
    for (int i = 0; i < 2; i++)
        #pragma unroll
        for (int j = 0; j < 8; j++)
            #pragma unroll
            for (int q = 0; q < 4; q++) acc[i][j][q] = 0.f;

    for (int c = 0; c < 4; c++) {
        if (c < 3) asm volatile("cp.async.wait_group 1;" ::: "memory");
        else       asm volatile("cp.async.wait_group 0;" ::: "memory");
        __syncthreads();
        uint32_t kvb = kvB + (c & 1) * 32768;
        #pragma unroll
        for (int k8 = 0; k8 < 8; k8++) {
            uint32_t af[2][4];
            #pragma unroll
            for (int mi = 0; mi < 2; mi++) {
                int row = (wm << 5) + (mi << 4) + (lane & 15);
                int u = ((c << 3) + k8) * 2 + (lane >> 4);
                ldsm4(af[mi], pB + (uint32_t)(row * 1024 + ((u ^ (row & 7)) << 4)));
            }
            uint32_t bf[4][4];
            #pragma unroll
            for (int g = 0; g < 4; g++) {
                int kl = (k8 << 4) + (lane & 7) + (((lane >> 3) & 1) << 3);
                int u = (wn << 3) + (g << 1) + (lane >> 4);
                ldsm4t(bf[g], kvb + (uint32_t)(kl * 256 + ((u ^ (kl & 7)) << 4)));
            }
            #pragma unroll
            for (int mi = 0; mi < 2; mi++)
                #pragma unroll
                for (int ni = 0; ni < 8; ni++)
                    mma16816(acc[mi][ni], af[mi], &bf[ni >> 1][(ni & 1) * 2]);
        }
        __syncthreads();
        if (c < 2) {
            ld128(kvB + (c & 1) * 32768, Vg + (long)(c + 2) * 128 * 2048);
            asm volatile("cp.async.commit_group;" ::: "memory");
        }
    }

    long cb = (long)b * 1048576 + (long)h * 128;
    int tg = lane >> 2, tc = lane & 3;
    #pragma unroll
    for (int mi = 0; mi < 2; mi++) {
        #pragma unroll
        for (int ni = 0; ni < 8; ni++) {
            int row = m0 + (wm << 5) + (mi << 4) + tg;
            int col = (wn << 6) + (ni << 3) + tc * 2;
            float* a4 = acc[mi][ni];
            __nv_bfloat162 p0 = __floats2bfloat162_rn(a4[0], a4[1]);
            __nv_bfloat162 p1 = __floats2bfloat162_rn(a4[2], a4[3]);
            *(__nv_bfloat162*)(d_ob + cb + (long)row * 2048 + col) = p0;
            *(__nv_bfloat162*)(d_ob + cb + (long)(row + 8) * 2048 + col) = p1;
        }
    }
}

__global__ void zero_acc_kernel() {
    if (threadIdx.x < 4) g_acc[threadIdx.x] = 0.0;
}

// x_t = sa*x_start + s1m*noise -> bf16; accumulate sum(x_start^2). 8 chunks/thread.
__global__ __launch_bounds__(256) void prep_kernel(
    const float* __restrict__ eseq, const float* __restrict__ elab,
    const float* __restrict__ noise, const float* __restrict__ sac,
    const float* __restrict__ s1mac, const int* __restrict__ tstep)
{
    double loc = 0.0;
    long base4 = (long)blockIdx.x * 2048 + threadIdx.x;
    #pragma unroll
    for (int i = 0; i < 8; i++) {
        long e = (base4 + i * 256) * 4;
        int d = (int)(e % D_);
        long bl = e / D_;
        int l = (int)(bl % L_);
        int b = (int)(bl / L_);
        float4 xs;
        if (l < LS_) xs = *(const float4*)(eseq + ((long)b * LS_ + l) * D_ + d);
        else         xs = *(const float4*)(elab + ((long)b * LL_ + (l - LS_)) * D_ + d);
        int t = tstep[b];
        float sa = sac[t], sm = s1mac[t];
        float4 nz = *(const float4*)(noise + e);
        __nv_bfloat162* ob = (__nv_bfloat162*)(d_xtb + e);
        ob[0] = __floats2bfloat162_rn(sa * xs.x + sm * nz.x, sa * xs.y + sm * nz.y);
        ob[1] = __floats2bfloat162_rn(sa * xs.z + sm * nz.z, sa * xs.w + sm * nz.w);
        loc += (double)xs.x * xs.x + (double)xs.y * xs.y +
               (double)xs.z * xs.z + (double)xs.w * xs.w;
    }
    double bs = blockReduceSumD(loc);
    if (threadIdx.x == 0) atomicAdd(&g_acc[0], bs);
}

// x_start[b,l,d] -> xT[d,b,l] (fp32, for contrast)
__global__ void transpose_kernel(const float* __restrict__ eseq,
                                 const float* __restrict__ elab)
{
    __shared__ float tile[32][33];
    int b = blockIdx.z;
    int d = blockIdx.x * 32 + threadIdx.x;
    int l = blockIdx.y * 32 + threadIdx.y;
    float v;
    if (l < LS_) v = eseq[((long)b * LS_ + l) * D_ + d];
    else         v = elab[((long)b * LL_ + (l - LS_)) * D_ + d];
    tile[threadIdx.y][threadIdx.x] = v;
    __syncthreads();
    int dw = blockIdx.x * 32 + threadIdx.y;
    int lw = blockIdx.y * 32 + threadIdx.x;
    d_xT[((long)dw * B_ + b) * L_ + lw] = tile[threadIdx.x][threadIdx.y];
}

// W[k,n] -> WT[n,k] bf16, 4 weights by blockIdx.z
__global__ void wt_kernel(const float* __restrict__ W0, const float* __restrict__ W1,
                          const float* __restrict__ W2, const float* __restrict__ W3)
{
    __shared__ float t[32][33];
    int zz = blockIdx.z;
    const float* W = (zz == 0) ? W0 : (zz == 1) ? W1 : (zz == 2) ? W2 : W3;
    int n = blockIdx.x * 32 + threadIdx.x;
    int k = blockIdx.y * 32 + threadIdx.y;
    t[threadIdx.y][threadIdx.x] = W[(long)k * 2048 + n];
    __syncthreads();
    int nn = blockIdx.x * 32 + threadIdx.y;
    int kk = blockIdx.y * 32 + threadIdx.x;
    d_wt[(long)zz * 4194304 + (long)nn * 2048 + kk] = __float2bfloat16(t[threadIdx.x][threadIdx.y]);
}

// per-channel contrastive loss. grid (D, 2): mode 0 = (seq,label), mode 1 = (label,label)
// float4-vectorized LDS (R10-proven)
__global__ __launch_bounds__(256) void contrast_kernel() {
    int d = blockIdx.x;
    int mode = blockIdx.y;
    __shared__ __align__(16) float f2s[32][260];
    __shared__ __align__(16) float f1s[8][260];
    __shared__ float inv2s[32];
    __shared__ double bsum[8];

    const float* base = d_xT + (long)d * B_ * L_;
    #pragma unroll
    for (int it = 0; it < 32; it++) {
        f2s[it][threadIdx.x] = base[(long)it * L_ + LS_ + threadIdx.x];
    }
    __syncthreads();
    if (threadIdx.x < 32) {
        const float4* r4 = (const float4*)&f2s[threadIdx.x][0];
        float s = 0.f;
        #pragma unroll 8
        for (int k = 0; k < 64; k++) {
            float4 x = r4[k];
            s += x.x * x.x + x.y * x.y + x.z * x.z + x.w * x.w;
        }
        inv2s[threadIdx.x] = rsqrtf(s);
    }
    __syncthreads();

    int warp = threadIdx.x >> 5, lane = threadIdx.x & 31;
    double wsum = 0.0;
    for (int tile = 0; tile < 4; tile++) {
        #pragma unroll
        for (int it = 0; it < 8; it++) {
            int bi = tile * 8 + it;
            f1s[it][threadIdx.x] = (mode == 0) ? base[(long)bi * L_ + threadIdx.x]
                                               : base[(long)bi * L_ + LS_ + threadIdx.x];
        }
        __syncthreads();
        const float4* a4 = (const float4*)&f1s[warp][0];
        const float4* b4 = (const float4*)&f2s[lane][0];
        float s = 0.f, p = 0.f;
        #pragma unroll 8
        for (int k = 0; k < 64; k++) {
            float4 a = a4[k];
            float4 b = b4[k];
            s += a.x * b.x + a.y * b.y + a.z * b.z + a.w * b.w;
            p += a.x * a.x + a.y * a.y + a.z * a.z + a.w * a.w;
        }
        float invn1 = rsqrtf(p);
        float logit = s * invn1 * inv2s[lane] * (1.0f / TAU_);
        float mx = logit;
        #pragma unroll
        for (int o = 16; o > 0; o >>= 1) mx = fmaxf(mx, __shfl_xor_sync(0xffffffffu, mx, o));
        float ex = __expf(logit - mx);
        float sm = ex;
        #pragma unroll
        for (int o = 16; o > 0; o >>= 1) sm += __shfl_xor_sync(0xffffffffu, sm, o);
        float lse = mx + __logf(sm);
        int gi = tile * 8 + warp;
        float diag = __shfl_sync(0xffffffffu, logit, gi);
        if (lane == 0) wsum += (double)(lse - diag);
        __syncthreads();
    }
    if (lane == 0) bsum[warp] = wsum;
    __syncthreads();
    if (threadIdx.x == 0) {
        double t = 0.0;
        #pragma unroll
        for (int w = 0; w < 8; w++) t += bsum[w];
        atomicAdd(&g_acc[2 + mode], t);
    }
}

__global__ void finalize_kernel(const float* __restrict__ sac, float* __restrict__ out) {
    double inv = 1.0 / (double)NEL;
    double saT = (double)sac[T_ - 1];
    double mse = g_acc[1] * inv;
    double tT  = saT * saT * g_acc[0] * inv;
    double con = (g_acc[2] + g_acc[3]) / (2048.0 * 32.0);
    out[0] = (float)(mse + tT + con);
}

// ---------------- launch ----------------
extern "C" void kernel_launch(void* const* d_in, const int* in_sizes, int n_in,
                              void* d_out, int out_size)
{
    const float* eseq  = (const float*)d_in[0];
    const float* elab  = (const float*)d_in[1];
    const float* noise = (const float*)d_in[2];
    const float* sac   = (const float*)d_in[3];
    const float* s1m   = (const float*)d_in[4];
    const float* Wq    = (const float*)d_in[5];
    const float* Wk    = (const float*)d_in[6];
    const float* Wv    = (const float*)d_in[7];
    const float* Wo    = (const float*)d_in[8];
    const int*   ts    = (const int*)d_in[9];
    float* out = (float*)d_out;

    __nv_bfloat16 *xtb, *wt, *ob;
    cudaGetSymbolAddress((void**)&xtb, d_xtb);
    cudaGetSymbolAddress((void**)&wt,  d_wt);
    cudaGetSymbolAddress((void**)&ob,  d_ob);

    cudaFuncSetAttribute((const void*)mma_gemm,
                         cudaFuncAttributeMaxDynamicSharedMemorySize, SMEM_G);
    cudaFuncSetAttribute((const void*)attn_fused,
                         cudaFuncAttributeMaxDynamicSharedMemorySize, ATTN_SMEM);

    static cudaStream_t s2 = nullptr;
    static cudaEvent_t eF = nullptr, eW = nullptr, eJ = nullptr;
    if (s2 == nullptr) {
        cudaStreamCreate(&s2);
        cudaEventCreateWithFlags(&eF, cudaEventDisableTiming);
        cudaEventCreateWithFlags(&eW, cudaEventDisableTiming);
        cudaEventCreateWithFlags(&eJ, cudaEventDisableTiming);
    }

    zero_acc_kernel<<<1, 32>>>();

    // fork: weight transpose + x_start transpose + contrast on side stream
    cudaEventRecord(eF, 0);
    cudaStreamWaitEvent(s2, eF, 0);
    wt_kernel<<<dim3(64, 64, 4), dim3(32, 32), 0, s2>>>(Wq, Wk, Wv, Wo);
    cudaEventRecord(eW, s2);
    transpose_kernel<<<dim3(64, 16, 32), dim3(32, 32), 0, s2>>>(eseq, elab);
    contrast_kernel<<<dim3(2048, 2), 256, 0, s2>>>();
    cudaEventRecord(eJ, s2);

    // main chain
    prep_kernel<<<4096, 256>>>(eseq, elab, noise, sac, s1m, ts);
    cudaStreamWaitEvent(0, eW, 0);

    // fused Q/K/V projection: N = 6144 over [WqT; WkT; WvT], M-tile 256
    mma_gemm<<<dim3(48, 64, 1), 512, SMEM_G>>>(
        xtb, 2048, wt, 2048, nullptr, 2048, 2048, 1.0f, 3, nullptr, nullptr);

    // fused attention: S = QK^T, softmax, O = PV
    attn_fused<<<dim3(4, 512), 256, ATTN_SMEM>>>();

    // model_output = O @ Wo^T, fused MSE vs x_start (no store)
    mma_gemm<<<dim3(16, 64, 1), 512, SMEM_G>>>(
        ob, 2048, wt + 3L * 4194304, 2048, nullptr, 2048, 2048, 1.0f, 2, eseq, elab);

    // join side chain, then finalize
    cudaStreamWaitEvent(0, eJ, 0);
    finalize_kernel<<<1, 1>>>(sac, out);
}

// round 13
// speedup vs baseline: 1.0344x; 1.0344x over previous
#include <cuda_runtime.h>
#include <cuda_bf16.h>
#include <cstdint>

// ---------------- problem constants ----------------
#define B_   32
#define LS_  256
#define LL_  256
#define L_   512
#define D_   2048
#define H_   16
#define DH_  128
#define T_   1000
#define TAU_ 0.07f
#define SCALE_ 0.08838834764831845f

#define NEL  33554432L   // B*L*D

// ---------------- scratch buffers (static, no allocation) ----------------
__device__ __nv_bfloat16 d_xtb[NEL];            // x_t bf16 [B,L,D]
__device__ __nv_bfloat16 d_wt[4L*2048*2048];    // WqT,WkT,WvT,WoT bf16 [N,K]
__device__ __nv_bfloat16 d_qb[NEL];             // Q bf16
__device__ __nv_bfloat16 d_kb[NEL];             // K bf16
__device__ __nv_bfloat16 d_vb[NEL];             // V bf16
__device__ __nv_bfloat16 d_ob[NEL];             // attn out bf16
__device__ float d_xT[NEL];                     // x_start^T [D,B,L] fp32
__device__ double g_acc[4];

// ---------------- reduction helper ----------------
__device__ __forceinline__ double blockReduceSumD(double v) {
    __shared__ double sh[8];
    #pragma unroll
    for (int o = 16; o > 0; o >>= 1) v += __shfl_down_sync(0xffffffffu, v, o);
    int lane = threadIdx.x & 31, w = threadIdx.x >> 5;
    if (lane == 0) sh[w] = v;
    __syncthreads();
    if (w == 0) {
        v = (lane < (int)(blockDim.x >> 5)) ? sh[lane] : 0.0;
        #pragma unroll
        for (int o = 4; o > 0; o >>= 1) v += __shfl_down_sync(0xffffffffu, v, o);
    }
    return v;
}

// ---------------- mma helpers ----------------
__device__ __forceinline__ void mma16816(float* c, const uint32_t* a, const uint32_t* b) {
    asm volatile(
        "mma.sync.aligned.m16n8k16.row.col.f32.bf16.bf16.f32 "
        "{%0,%1,%2,%3}, {%4,%5,%6,%7}, {%8,%9}, {%0,%1,%2,%3};"
        : "+f"(c[0]), "+f"(c[1]), "+f"(c[2]), "+f"(c[3])
        : "r"(a[0]), "r"(a[1]), "r"(a[2]), "r"(a[3]), "r"(b[0]), "r"(b[1]));
}
__device__ __forceinline__ void ldsm4(uint32_t* f, uint32_t addr) {
    asm volatile("ldmatrix.sync.aligned.m8n8.x4.shared.b16 {%0,%1,%2,%3}, [%4];"
                 : "=r"(f[0]), "=r"(f[1]), "=r"(f[2]), "=r"(f[3]) : "r"(addr));
}
__device__ __forceinline__ void ldsm4t(uint32_t* f, uint32_t addr) {
    asm volatile("ldmatrix.sync.aligned.m8n8.x4.trans.shared.b16 {%0,%1,%2,%3}, [%4];"
                 : "=r"(f[0]), "=r"(f[1]), "=r"(f[2]), "=r"(f[3]) : "r"(addr));
}

// ---------------- batched bf16 MMA GEMM (R7/R11-proven config) ----------------
// C = alpha * A[M,K] @ B[N,K]^T. 128x128 CTA tile, 32x64 warp tile, BK=64,
// 3-stage cp.async, one sync per k-step, 256 threads (8 warps), 2 CTA/SM.
// outMode: 1=bf16 store, 2=fused MSE vs concat(eseq,elab), 3=QKV split.
#define SROWK 144   // 128B data + 16B pad
#define G_STAGES 3
#define G_STAGE_BYTES ((128 + 128) * SROWK)
#define SMEM_G (G_STAGES * G_STAGE_BYTES)   // 110592

__global__ __launch_bounds__(256, 2) void mma_gemm(
    const __nv_bfloat16* __restrict__ A, int lda,
    const __nv_bfloat16* __restrict__ Bm, int ldb,
    void* __restrict__ Cv, int ldc,
    int K, float alpha, int outMode,
    const float* __restrict__ xseq, const float* __restrict__ xlab)
{
    extern __shared__ __align__(16) char dsm[];
    uint32_t sbase = (uint32_t)__cvta_generic_to_shared(dsm);

    int tid = threadIdx.x, lane = tid & 31, wid = tid >> 5;
    int m0 = blockIdx.y << 7, n0 = blockIdx.x << 7;
    int wm = wid & 3, wn = wid >> 2;   // 4 M-warps x 2 N-warps

    const __nv_bfloat16* Ag = A + (long)m0 * lda;
    const __nv_bfloat16* Bg = Bm + (long)n0 * ldb;

    float acc[2][8][4];
    #pragma unroll
    for (int i = 0; i < 2; i++)
        #pragma unroll
        for (int j = 0; j < 8; j++)
            #pragma unroll
            for (int q = 0; q < 4; q++) acc[i][j][q] = 0.f;

    auto load_tile = [&](int sidx, int buf) {
        const __nv_bfloat16* Ab = Ag + (long)sidx * 64;
        const __nv_bfloat16* Bb = Bg + (long)sidx * 64;
        uint32_t stA = sbase + buf * G_STAGE_BYTES;
        uint32_t stB = stA + 128 * SROWK;
        #pragma unroll
        for (int i = 0; i < 4; i++) {
            int ch = i * 256 + tid;
            int r = ch >> 3, c = ch & 7;
            uint32_t so = (uint32_t)(r * SROWK + c * 16);
            const void* ga = Ab + (long)r * lda + c * 8;
            asm volatile("cp.async.cg.shared.global [%0], [%1], 16;" :: "r"(stA + so), "l"(ga));
            const void* gb = Bb + (long)r * ldb + c * 8;
            asm volatile("cp.async.cg.shared.global [%0], [%1], 16;" :: "r"(stB + so), "l"(gb));
        }
    };

    int nt = K >> 6;
    #pragma unroll
    for (int i = 0; i < G_STAGES - 1; i++) {
        if (i < nt) load_tile(i, i);
        asm volatile("cp.async.commit_group;" ::: "memory");
    }

    for (int s = 0; s < nt; s++) {
        asm volatile("cp.async.wait_group %0;" :: "n"(G_STAGES - 2) : "memory");
        __syncthreads();
        int pf = s + G_STAGES - 1;
        if (pf < nt) load_tile(pf, pf % G_STAGES);
        asm volatile("cp.async.commit_group;" ::: "memory");

        uint32_t baseA = sbase + (s % G_STAGES) * G_STAGE_BYTES;
        uint32_t baseB = baseA + 128 * SROWK;
        #pragma unroll
        for (int kk = 0; kk < 4; kk++) {
            uint32_t af[2][4];
            #pragma unroll
            for (int mi = 0; mi < 2; mi++) {
                int row = (wm << 5) + (mi << 4) + (lane & 15);
                uint32_t ad = baseA + (uint32_t)(row * SROWK + (kk << 5) + ((lane >> 4) << 4));
                ldsm4(af[mi], ad);
            }
            uint32_t bf[4][4];
            #pragma unroll
            for (int g = 0; g < 4; g++) {
                int nrow = (wn << 6) + (g << 4) + ((lane >> 4) << 3) + (lane & 7);
                uint32_t bd = baseB + (uint32_t)(nrow * SROWK + (kk << 5) + (((lane >> 3) & 1) << 4));
                ldsm4(bf[g], bd);
            }
            #pragma unroll
            for (int mi = 0; mi < 2; mi++)
                #pragma unroll
                for (int ni = 0; ni < 8; ni++)
                    mma16816(acc[mi][ni], af[mi], &bf[ni >> 1][(ni & 1) * 2]);
        }
    }

    // epilogue
    int tg = lane >> 2, tc = lane & 3;
    if (outMode == 2) {
        float lsum = 0.f;
        #pragma unroll
        for (int mi = 0; mi < 2; mi++) {
            #pragma unroll
            for (int ni = 0; ni < 8; ni++) {
                int row = m0 + (wm << 5) + (mi << 4) + tg;
                int col = n0 + (wn << 6) + (ni << 3) + tc * 2;
                float* a4 = acc[mi][ni];
                #pragma unroll
                for (int h = 0; h < 2; h++) {
                    int r = row + h * 8;
                    int b = r >> 9, l = r & 511;
                    const float* xp = (l < LS_)
                        ? (xseq + ((long)b * LS_ + l) * D_ + col)
                        : (xlab + ((long)b * LL_ + (l - LS_)) * D_ + col);
                    float2 x2 = *(const float2*)xp;
                    float d0 = x2.x - a4[2 * h];
                    float d1 = x2.y - a4[2 * h + 1];
                    lsum += d0 * d0 + d1 * d1;
                }
            }
        }
        double bs = blockReduceSumD((double)lsum);
        if (tid == 0) atomicAdd(&g_acc[1], bs);
        return;
    }
    __nv_bfloat16* C;
    int nb = n0;
    if (outMode == 3) {
        int which = n0 >> 11;
        C = (which == 0) ? d_qb : ((which == 1) ? d_kb : d_vb);
        nb = n0 & 2047;
    } else {
        C = (__nv_bfloat16*)Cv;
    }
    #pragma unroll
    for (int mi = 0; mi < 2; mi++) {
        #pragma unroll
        for (int ni = 0; ni < 8; ni++) {
            int row = m0 + (wm << 5) + (mi << 4) + tg;
            int col = nb + (wn << 6) + (ni << 3) + tc * 2;
            float* a4 = acc[mi][ni];
            __nv_bfloat162 p0 = __floats2bfloat162_rn(a4[0] * alpha, a4[1] * alpha);
            __nv_bfloat162 p1 = __floats2bfloat162_rn(a4[2] * alpha, a4[3] * alpha);
            *(__nv_bfloat162*)(C + (long)row * ldc + col) = p0;
            *(__nv_bfloat162*)(C + (long)(row + 8) * ldc + col) = p1;
        }
    }
}

// ---------------- fully fused attention: S = QK^T -> softmax -> O = P V ----------------
#define ATTN_SMEM 229376

__global__ __launch_bounds__(256, 1) void attn_fused() {
    extern __shared__ __align__(16) char dsm[];
    uint32_t base = (uint32_t)__cvta_generic_to_shared(dsm);
    uint32_t pB = base;
    uint32_t kvB = base + 131072;
    uint32_t qB = base + 196608;

    int tid = threadIdx.x, lane = tid & 31, wid = tid >> 5;
    int z = blockIdx.y, m0 = blockIdx.x << 7;
    int b = z >> 4, h = z & 15;
    const __nv_bfloat16* Qg = d_qb + ((long)b * 512 + m0) * 2048 + h * 128;
    const __nv_bfloat16* Kg = d_kb + (long)b * 512 * 2048 + h * 128;
    const __nv_bfloat16* Vg = d_vb + (long)b * 512 * 2048 + h * 128;
    int wm = wid & 3, wn = wid >> 2;

    auto ld128 = [&](uint32_t dst, const __nv_bfloat16* src) {
        #pragma unroll
        for (int i = 0; i < 8; i++) {
            int id = i * 256 + tid;
            int r = id >> 4, u = id & 15;
            const void* g = src + (long)r * 2048 + u * 8;
            uint32_t d = dst + (uint32_t)(r * 256 + ((u ^ (r & 7)) << 4));
            asm volatile("cp.async.cg.shared.global [%0], [%1], 16;" :: "r"(d), "l"(g));
        }
    };

    ld128(qB, Qg);
    asm volatile("cp.async.commit_group;" ::: "memory");
    ld128(kvB, Kg);
    asm volatile("cp.async.commit_group;" ::: "memory");
    ld128(kvB + 32768, Kg + 128L * 2048);
    asm volatile("cp.async.commit_group;" ::: "memory");

    // ---- phase 1: S chunks -> P (bf16, scaled) ----
    for (int c = 0; c < 4; c++) {
        asm volatile("cp.async.wait_group 1;" ::: "memory");
        __syncthreads();
        uint32_t kvb = kvB + (c & 1) * 32768;
        float acc[2][8][4];
        #pragma unroll
        for (int i = 0; i < 2; i++)
            #pragma unroll
            for (int j = 0; j < 8; j++)
                #pragma unroll
                for (int q = 0; q < 4; q++) acc[i][j][q] = 0.f;
        #pragma unroll
        for (int k8 = 0; k8 < 8; k8++) {
            uint32_t af[2][4];
            #pragma unroll
            for (int mi = 0; mi < 2; mi++) {
                int row = (wm << 5) + (mi << 4) + (lane & 15);
                int u = (k8 << 1) + (lane >> 4);
                ldsm4(af[mi], qB + (uint32_t)(row * 256 + ((u ^ (row & 7)) << 4)));
            }
            uint32_t bf[4][4];
            #pragma unroll
            for (int g = 0; g < 4; g++) {
                int nrow = (wn << 6) + (g << 4) + ((lane >> 4) << 3) + (lane & 7);
                int u = (k8 << 1) + ((lane >> 3) & 1);
                ldsm4(bf[g], kvb + (uint32_t)(nrow * 256 + ((u ^ (nrow & 7)) << 4)));
            }
            #pragma unroll
            for (int mi = 0; mi < 2; mi++)
                #pragma unroll
                for (int ni = 0; ni < 8; ni++)
                    mma16816(acc[mi][ni], af[mi], &bf[ni >> 1][(ni & 1) * 2]);
        }
        int tg = lane >> 2, tc = lane & 3;
        #pragma unroll
        for (int mi = 0; mi < 2; mi++) {
            #pragma unroll
            for (int ni = 0; ni < 8; ni++) {
                int row = (wm << 5) + (mi << 4) + tg;
                int ub = (c << 4) + (wn << 3) + ni;
                float* a4 = acc[mi][ni];
                #pragma unroll
                for (int h2 = 0; h2 < 2; h2++) {
                    int r2 = row + h2 * 8;
                    uint32_t off = (uint32_t)(r2 * 1024 + ((ub ^ (r2 & 7)) << 4) + tc * 4);
                    *(__nv_bfloat162*)(dsm + off) = __floats2bfloat162_rn(
                        a4[2 * h2] * SCALE_, a4[2 * h2 + 1] * SCALE_);
                }
            }
        }
        __syncthreads();
        if (c < 2)       ld128(kvB + (c & 1) * 32768, Kg + (long)(c + 2) * 128 * 2048);
        else if (c == 2) ld128(kvB, Vg);
        else             ld128(kvB + 32768, Vg + 128L * 2048);
        asm volatile("cp.async.commit_group;" ::: "memory");
    }

    // ---- softmax in place on P ----
    for (int rr = 0; rr < 16; rr++) {
        int row = wid * 16 + rr;
        int x = row & 7;
        uint32_t a0 = (uint32_t)(row * 1024 + ((lane ^ x) << 4));
        uint32_t a1 = (uint32_t)(row * 1024 + (((lane + 32) ^ x) << 4));
        uint4 u0 = *(uint4*)(dsm + a0);
        uint4 u1 = *(uint4*)(dsm + a1);
        float v[16];
        const uint32_t* w0 = (const uint32_t*)&u0;
        const uint32_t* w1 = (const uint32_t*)&u1;
        #pragma unroll
        for (int j = 0; j < 4; j++) {
            __nv_bfloat162 h0 = *(__nv_bfloat162*)&w0[j];
            __nv_bfloat162 h1 = *(__nv_bfloat162*)&w1[j];
            v[2 * j]     = __bfloat162float(h0.x);
            v[2 * j + 1] = __bfloat162float(h0.y);
            v[8 + 2 * j] = __bfloat162float(h1.x);
            v[9 + 2 * j] = __bfloat162float(h1.y);
        }
        float m = v[0];
        #pragma unroll
        for (int j = 1; j < 16; j++) m = fmaxf(m, v[j]);
        #pragma unroll
        for (int o = 16; o > 0; o >>= 1) m = fmaxf(m, __shfl_xor_sync(0xffffffffu, m, o));
        float s = 0.f;
        #pragma unroll
        for (int j = 0; j < 16; j++) { v[j] = __expf(v[j] - m); s += v[j]; }
        #pragma unroll
        for (int o = 16; o > 0; o >>= 1) s += __shfl_xor_sync(0xffffffffu, s, o);
        float inv = 1.0f / s;
        uint32_t pk[8];
        #pragma unroll
        for (int j = 0; j < 4; j++) {
            __nv_bfloat162 pa = __floats2bfloat162_rn(v[2 * j] * inv, v[2 * j + 1] * inv);
            __nv_bfloat162 pb = __floats2bfloat162_rn(v[8 + 2 * j] * inv, v[9 + 2 * j] * inv);
            pk[j] = *(uint32_t*)&pa;
            pk[4 + j] = *(uint32_t*)&pb;
        }
        *(uint4*)(dsm + a0) = make_uint4(pk[0], pk[1], pk[2], pk[3]);
        *(uint4*)(dsm + a1) = make_uint4(pk[4], pk[5], pk[6], pk[7]);
    }

    // ---- phase 2: O = P @ V ----
    float acc[2][8][4];
    #pragma unroll
    for (int i = 0; i < 2; i++)
        #pragma unroll
        for (int j = 0; j < 8; j++)
            #pragma unroll
            for (int q = 0; q < 4; q++) acc[i][j][q] = 0.f;

    for (int c = 0; c < 4; c++) {
        if (c < 3) asm volatile("cp.async.wait_group 1;" ::: "memory");
        else       asm volatile("cp.async.wait_group 0;" ::: "memory");
        __syncthreads();
        uint32_t kvb = kvB + (c & 1) * 32768;
        #pragma unroll
        for (int k8 = 0; k8 < 8; k8++) {
            uint32_t af[2][4];
            #pragma unroll
            for (int mi = 0; mi < 2; mi++) {
                int row = (wm << 5) + (mi << 4) + (lane & 15);
                int u = ((c << 3) + k8) * 2 + (lane >> 4);
                ldsm4(af[mi], pB + (uint32_t)(row * 1024 + ((u ^ (row & 7)) << 4)));
            }
            uint32_t bf[4][4];
            #pragma unroll
            for (int g = 0; g < 4; g++) {
                int kl = (k8 << 4) + (lane & 7) + (((lane >> 3) & 1) << 3);
                int u = (wn << 3) + (g << 1) + (lane >> 4);
                ldsm4t(bf[g], kvb + (uint32_t)(kl * 256 + ((u ^ (kl & 7)) << 4)));
            }
            #pragma unroll
            for (int mi = 0; mi < 2; mi++)
                #pragma unroll
                for (int ni = 0; ni < 8; ni++)
                    mma16816(acc[mi][ni], af[mi], &bf[ni >> 1][(ni & 1) * 2]);
        }
        __syncthreads();
        if (c < 2) {
            ld128(kvB + (c & 1) * 32768, Vg + (long)(c + 2) * 128 * 2048);
            asm volatile("cp.async.commit_group;" ::: "memory");
        }
    }

    long cb = (long)b * 1048576 + (long)h * 128;
    int tg = lane >> 2, tc = lane & 3;
    #pragma unroll
    for (int mi = 0; mi < 2; mi++) {
        #pragma unroll
        for (int ni = 0; ni < 8; ni++) {
            int row = m0 + (wm << 5) + (mi << 4) + tg;
            int col = (wn << 6) + (ni << 3) + tc * 2;
            float* a4 = acc[mi][ni];
            __nv_bfloat162 p0 = __floats2bfloat162_rn(a4[0], a4[1]);
            __nv_bfloat162 p1 = __floats2bfloat162_rn(a4[2], a4[3]);
            *(__nv_bfloat162*)(d_ob + cb + (long)row * 2048 + col) = p0;
            *(__nv_bfloat162*)(d_ob + cb + (long)(row + 8) * 2048 + col) = p1;
        }
    }
}

__global__ void zero_acc_kernel() {
    if (threadIdx.x < 4) g_acc[threadIdx.x] = 0.0;
}

// x_t = sa*x_start + s1m*noise -> bf16; accumulate sum(x_start^2). 8 chunks/thread.
__global__ __launch_bounds__(256) void prep_kernel(
    const float* __restrict__ eseq, const float* __restrict__ elab,
    const float* __restrict__ noise, const float* __restrict__ sac,
    const float* __restrict__ s1mac, const int* __restrict__ tstep)
{
    double loc = 0.0;
    long base4 = (long)blockIdx.x * 2048 + threadIdx.x;
    #pragma unroll
    for (int i = 0; i < 8; i++) {
        long e = (base4 + i * 256) * 4;
        int d = (int)(e % D_);
        long bl = e / D_;
        int l = (int)(bl % L_);
        int b = (int)(bl / L_);
        float4 xs;
        if (l < LS_) xs = *(const float4*)(eseq + ((long)b * LS_ + l) * D_ + d);
        else         xs = *(const float4*)(elab + ((long)b * LL_ + (l - LS_)) * D_ + d);
        int t = tstep[b];
        float sa = sac[t], sm = s1mac[t];
        float4 nz = *(const float4*)(noise + e);
        __nv_bfloat162* ob = (__nv_bfloat162*)(d_xtb + e);
        ob[0] = __floats2bfloat162_rn(sa * xs.x + sm * nz.x, sa * xs.y + sm * nz.y);
        ob[1] = __floats2bfloat162_rn(sa * xs.z + sm * nz.z, sa * xs.w + sm * nz.w);
        loc += (double)xs.x * xs.x + (double)xs.y * xs.y +
               (double)xs.z * xs.z + (double)xs.w * xs.w;
    }
    double bs = blockReduceSumD(loc);
    if (threadIdx.x == 0) atomicAdd(&g_acc[0], bs);
}

// x_start[b,l,d] -> xT[d,b,l] (fp32, for contrast)
__global__ void transpose_kernel(const float* __restrict__ eseq,
                                 const float* __restrict__ elab)
{
    __shared__ float tile[32][33];
    int b = blockIdx.z;
    int d = blockIdx.x * 32 + threadIdx.x;
    int l = blockIdx.y * 32 + threadIdx.y;
    float v;
    if (l < LS_) v = eseq[((long)b * LS_ + l) * D_ + d];
    else         v = elab[((long)b * LL_ + (l - LS_)) * D_ + d];
    tile[threadIdx.y][threadIdx.x] = v;
    __syncthreads();
    int dw = blockIdx.x * 32 + threadIdx.y;
    int lw = blockIdx.y * 32 + threadIdx.x;
    d_xT[((long)dw * B_ + b) * L_ + lw] = tile[threadIdx.x][threadIdx.y];
}

// W[k,n] -> WT[n,k] bf16, 4 weights by blockIdx.z
__global__ void wt_kernel(const float* __restrict__ W0, const float* __restrict__ W1,
                          const float* __restrict__ W2, const float* __restrict__ W3)
{
    __shared__ float t[32][33];
    int zz = blockIdx.z;
    const float* W = (zz == 0) ? W0 : (zz == 1) ? W1 : (zz == 2) ? W2 : W3;
    int n = blockIdx.x * 32 + threadIdx.x;
    int k = blockIdx.y * 32 + threadIdx.y;
    t[threadIdx.y][threadIdx.x] = W[(long)k * 2048 + n];
    __syncthreads();
    int nn = blockIdx.x * 32 + threadIdx.y;
    int kk = blockIdx.y * 32 + threadIdx.x;
    d_wt[(long)zz * 4194304 + (long)nn * 2048 + kk] = __float2bfloat16(t[threadIdx.x][threadIdx.y]);
}

// per-channel contrastive loss. grid (D, 2): mode 0 = (seq,label), mode 1 = (label,label)
// float4-vectorized LDS (R10-proven)
__global__ __launch_bounds__(256) void contrast_kernel() {
    int d = blockIdx.x;
    int mode = blockIdx.y;
    __shared__ __align__(16) float f2s[32][260];
    __shared__ __align__(16) float f1s[8][260];
    __shared__ float inv2s[32];
    __shared__ double bsum[8];

    const float* base = d_xT + (long)d * B_ * L_;
    #pragma unroll
    for (int it = 0; it < 32; it++) {
        f2s[it][threadIdx.x] = base[(long)it * L_ + LS_ + threadIdx.x];
    }
    __syncthreads();
    if (threadIdx.x < 32) {
        const float4* r4 = (const float4*)&f2s[threadIdx.x][0];
        float s = 0.f;
        #pragma unroll 8
        for (int k = 0; k < 64; k++) {
            float4 x = r4[k];
            s += x.x * x.x + x.y * x.y + x.z * x.z + x.w * x.w;
        }
        inv2s[threadIdx.x] = rsqrtf(s);
    }
    __syncthreads();

    int warp = threadIdx.x >> 5, lane = threadIdx.x & 31;
    double wsum = 0.0;
    for (int tile = 0; tile < 4; tile++) {
        #pragma unroll
        for (int it = 0; it < 8; it++) {
            int bi = tile * 8 + it;
            f1s[it][threadIdx.x] = (mode == 0) ? base[(long)bi * L_ + threadIdx.x]
                                               : base[(long)bi * L_ + LS_ + threadIdx.x];
        }
        __syncthreads();
        const float4* a4 = (const float4*)&f1s[warp][0];
        const float4* b4 = (const float4*)&f2s[lane][0];
        float s = 0.f, p = 0.f;
        #pragma unroll 8
        for (int k = 0; k < 64; k++) {
            float4 a = a4[k];
            float4 b = b4[k];
            s += a.x * b.x + a.y * b.y + a.z * b.z + a.w * b.w;
            p += a.x * a.x + a.y * a.y + a.z * a.z + a.w * a.w;
        }
        float invn1 = rsqrtf(p);
        float logit = s * invn1 * inv2s[lane] * (1.0f / TAU_);
        float mx = logit;
        #pragma unroll
        for (int o = 16; o > 0; o >>= 1) mx = fmaxf(mx, __shfl_xor_sync(0xffffffffu, mx, o));
        float ex = __expf(logit - mx);
        float sm = ex;
        #pragma unroll
        for (int o = 16; o > 0; o >>= 1) sm += __shfl_xor_sync(0xffffffffu, sm, o);
        float lse = mx + __logf(sm);
        int gi = tile * 8 + warp;
        float diag = __shfl_sync(0xffffffffu, logit, gi);
        if (lane == 0) wsum += (double)(lse - diag);
        __syncthreads();
    }
    if (lane == 0) bsum[warp] = wsum;
    __syncthreads();
    if (threadIdx.x == 0) {
        double t = 0.0;
        #pragma unroll
        for (int w = 0; w < 8; w++) t += bsum[w];
        atomicAdd(&g_acc[2 + mode], t);
    }
}

__global__ void finalize_kernel(const float* __restrict__ sac, float* __restrict__ out) {
    double inv = 1.0 / (double)NEL;
    double saT = (double)sac[T_ - 1];
    double mse = g_acc[1] * inv;
    double tT  = saT * saT * g_acc[0] * inv;
    double con = (g_acc[2] + g_acc[3]) / (2048.0 * 32.0);
    out[0] = (float)(mse + tT + con);
}

// ---------------- launch ----------------
extern "C" void kernel_launch(void* const* d_in, const int* in_sizes, int n_in,
                              void* d_out, int out_size)
{
    const float* eseq  = (const float*)d_in[0];
    const float* elab  = (const float*)d_in[1];
    const float* noise = (const float*)d_in[2];
    const float* sac   = (const float*)d_in[3];
    const float* s1m   = (const float*)d_in[4];
    const float* Wq    = (const float*)d_in[5];
    const float* Wk    = (const float*)d_in[6];
    const float* Wv    = (const float*)d_in[7];
    const float* Wo    = (const float*)d_in[8];
    const int*   ts    = (const int*)d_in[9];
    float* out = (float*)d_out;

    __nv_bfloat16 *xtb, *wt, *ob;
    cudaGetSymbolAddress((void**)&xtb, d_xtb);
    cudaGetSymbolAddress((void**)&wt,  d_wt);
    cudaGetSymbolAddress((void**)&ob,  d_ob);

    cudaFuncSetAttribute((const void*)mma_gemm,
                         cudaFuncAttributeMaxDynamicSharedMemorySize, SMEM_G);
    cudaFuncSetAttribute((const void*)attn_fused,
                         cudaFuncAttributeMaxDynamicSharedMemorySize, ATTN_SMEM);

    static cudaStream_t s2 = nullptr;
    static cudaEvent_t eF = nullptr, eW = nullptr, eJ = nullptr;
    if (s2 == nullptr) {
        cudaStreamCreate(&s2);
        cudaEventCreateWithFlags(&eF, cudaEventDisableTiming);
        cudaEventCreateWithFlags(&eW, cudaEventDisableTiming);
        cudaEventCreateWithFlags(&eJ, cudaEventDisableTiming);
    }

    zero_acc_kernel<<<1, 32>>>();

    // fork: weight transpose + x_start transpose + contrast on side stream
    cudaEventRecord(eF, 0);
    cudaStreamWaitEvent(s2, eF, 0);
    wt_kernel<<<dim3(64, 64, 4), dim3(32, 32), 0, s2>>>(Wq, Wk, Wv, Wo);
    cudaEventRecord(eW, s2);
    transpose_kernel<<<dim3(64, 16, 32), dim3(32, 32), 0, s2>>>(eseq, elab);
    contrast_kernel<<<dim3(2048, 2), 256, 0, s2>>>();
    cudaEventRecord(eJ, s2);

    // main chain
    prep_kernel<<<4096, 256>>>(eseq, elab, noise, sac, s1m, ts);
    cudaStreamWaitEvent(0, eW, 0);

    // fused Q/K/V projection: N = 6144 over [WqT; WkT; WvT]
    mma_gemm<<<dim3(48, 128, 1), 256, SMEM_G>>>(
        xtb, 2048, wt, 2048, nullptr, 2048, 2048, 1.0f, 3, nullptr, nullptr);

    // fused attention: S = QK^T, softmax, O = PV
    attn_fused<<<dim3(4, 512), 256, ATTN_SMEM>>>();

    // model_output = O @ Wo^T, fused MSE vs x_start (no store)
    mma_gemm<<<dim3(16, 128, 1), 256, SMEM_G>>>(
        ob, 2048, wt + 3L * 4194304, 2048, nullptr, 2048, 2048, 1.0f, 2, eseq, elab);

    // join side chain, then finalize
    cudaStreamWaitEvent(0, eJ, 0);
    finalize_kernel<<<1, 1>>>(sac, out);
}

// round 14
// speedup vs baseline: 1.0675x; 1.0320x over previous
#include <cuda_runtime.h>
#include <cuda_bf16.h>
#include <cstdint>

// ---------------- problem constants ----------------
#define B_   32
#define LS_  256
#define LL_  256
#define L_   512
#define D_   2048
#define H_   16
#define DH_  128
#define T_   1000
#define TAU_ 0.07f
#define SCALE_ 0.08838834764831845f

#define NEL  33554432L   // B*L*D

// ---------------- scratch buffers (static, no allocation) ----------------
__device__ __nv_bfloat16 d_xtb[NEL];            // x_t bf16 [B,L,D]
__device__ __nv_bfloat16 d_wt[4L*2048*2048];    // WqT,WkT,WvT,WoT bf16 [N,K]
__device__ __nv_bfloat16 d_qb[NEL];             // Q bf16
__device__ __nv_bfloat16 d_kb[NEL];             // K bf16
__device__ __nv_bfloat16 d_vb[NEL];             // V bf16
__device__ __nv_bfloat16 d_ob[NEL];             // attn out bf16
__device__ float d_xT[NEL];                     // x_start^T [D,B,L] fp32
__device__ double g_acc[4];

// ---------------- reduction helper ----------------
__device__ __forceinline__ double blockReduceSumD(double v) {
    __shared__ double sh[8];
    #pragma unroll
    for (int o = 16; o > 0; o >>= 1) v += __shfl_down_sync(0xffffffffu, v, o);
    int lane = threadIdx.x & 31, w = threadIdx.x >> 5;
    if (lane == 0) sh[w] = v;
    __syncthreads();
    if (w == 0) {
        v = (lane < (int)(blockDim.x >> 5)) ? sh[lane] : 0.0;
        #pragma unroll
        for (int o = 4; o > 0; o >>= 1) v += __shfl_down_sync(0xffffffffu, v, o);
    }
    return v;
}

// ---------------- mma helpers ----------------
__device__ __forceinline__ void mma16816(float* c, const uint32_t* a, const uint32_t* b) {
    asm volatile(
        "mma.sync.aligned.m16n8k16.row.col.f32.bf16.bf16.f32 "
        "{%0,%1,%2,%3}, {%4,%5,%6,%7}, {%8,%9}, {%0,%1,%2,%3};"
        : "+f"(c[0]), "+f"(c[1]), "+f"(c[2]), "+f"(c[3])
        : "r"(a[0]), "r"(a[1]), "r"(a[2]), "r"(a[3]), "r"(b[0]), "r"(b[1]));
}
__device__ __forceinline__ void ldsm4(uint32_t* f, uint32_t addr) {
    asm volatile("ldmatrix.sync.aligned.m8n8.x4.shared.b16 {%0,%1,%2,%3}, [%4];"
                 : "=r"(f[0]), "=r"(f[1]), "=r"(f[2]), "=r"(f[3]) : "r"(addr));
}
__device__ __forceinline__ void ldsm4t(uint32_t* f, uint32_t addr) {
    asm volatile("ldmatrix.sync.aligned.m8n8.x4.trans.shared.b16 {%0,%1,%2,%3}, [%4];"
                 : "=r"(f[0]), "=r"(f[1]), "=r"(f[2]), "=r"(f[3]) : "r"(addr));
}
__device__ __forceinline__ uint32_t f2tf32(float x) {
    uint32_t r;
    asm("cvt.rna.tf32.f32 %0, %1;" : "=r"(r) : "f"(x));
    return r;
}

// ---------------- batched bf16 MMA GEMM (R7/R11-proven config) ----------------
// C = alpha * A[M,K] @ B[N,K]^T. 128x128 CTA tile, 32x64 warp tile, BK=64,
// 3-stage cp.async, one sync per k-step, 256 threads (8 warps), 2 CTA/SM.
// outMode: 1=bf16 store, 2=fused MSE vs concat(eseq,elab), 3=QKV split.
#define SROWK 144   // 128B data + 16B pad
#define G_STAGES 3
#define G_STAGE_BYTES ((128 + 128) * SROWK)
#define SMEM_G (G_STAGES * G_STAGE_BYTES)   // 110592

__global__ __launch_bounds__(256, 2) void mma_gemm(
    const __nv_bfloat16* __restrict__ A, int lda,
    const __nv_bfloat16* __restrict__ Bm, int ldb,
    void* __restrict__ Cv, int ldc,
    int K, float alpha, int outMode,
    const float* __restrict__ xseq, const float* __restrict__ xlab)
{
    extern __shared__ __align__(16) char dsm[];
    uint32_t sbase = (uint32_t)__cvta_generic_to_shared(dsm);

    int tid = threadIdx.x, lane = tid & 31, wid = tid >> 5;
    int m0 = blockIdx.y << 7, n0 = blockIdx.x << 7;
    int wm = wid & 3, wn = wid >> 2;   // 4 M-warps x 2 N-warps

    const __nv_bfloat16* Ag = A + (long)m0 * lda;
    const __nv_bfloat16* Bg = Bm + (long)n0 * ldb;

    float acc[2][8][4];
    #pragma unroll
    for (int i = 0; i < 2; i++)
        #pragma unroll
        for (int j = 0; j < 8; j++)
            #pragma unroll
            for (int q = 0; q < 4; q++) acc[i][j][q] = 0.f;

    auto load_tile = [&](int sidx, int buf) {
        const __nv_bfloat16* Ab = Ag + (long)sidx * 64;
        const __nv_bfloat16* Bb = Bg + (long)sidx * 64;
        uint32_t stA = sbase + buf * G_STAGE_BYTES;
        uint32_t stB = stA + 128 * SROWK;
        #pragma unroll
        for (int i = 0; i < 4; i++) {
            int ch = i * 256 + tid;
            int r = ch >> 3, c = ch & 7;
            uint32_t so = (uint32_t)(r * SROWK + c * 16);
            const void* ga = Ab + (long)r * lda + c * 8;
            asm volatile("cp.async.cg.shared.global [%0], [%1], 16;" :: "r"(stA + so), "l"(ga));
            const void* gb = Bb + (long)r * ldb + c * 8;
            asm volatile("cp.async.cg.shared.global [%0], [%1], 16;" :: "r"(stB + so), "l"(gb));
        }
    };

    int nt = K >> 6;
    #pragma unroll
    for (int i = 0; i < G_STAGES - 1; i++) {
        if (i < nt) load_tile(i, i);
        asm volatile("cp.async.commit_group;" ::: "memory");
    }

    for (int s = 0; s < nt; s++) {
        asm volatile("cp.async.wait_group %0;" :: "n"(G_STAGES - 2) : "memory");
        __syncthreads();
        int pf = s + G_STAGES - 1;
        if (pf < nt) load_tile(pf, pf % G_STAGES);
        asm volatile("cp.async.commit_group;" ::: "memory");

        uint32_t baseA = sbase + (s % G_STAGES) * G_STAGE_BYTES;
        uint32_t baseB = baseA + 128 * SROWK;
        #pragma unroll
        for (int kk = 0; kk < 4; kk++) {
            uint32_t af[2][4];
            #pragma unroll
            for (int mi = 0; mi < 2; mi++) {
                int row = (wm << 5) + (mi << 4) + (lane & 15);
                uint32_t ad = baseA + (uint32_t)(row * SROWK + (kk << 5) + ((lane >> 4) << 4));
                ldsm4(af[mi], ad);
            }
            uint32_t bf[4][4];
            #pragma unroll
            for (int g = 0; g < 4; g++) {
                int nrow = (wn << 6) + (g << 4) + ((lane >> 4) << 3) + (lane & 7);
                uint32_t bd = baseB + (uint32_t)(nrow * SROWK + (kk << 5) + (((lane >> 3) & 1) << 4));
                ldsm4(bf[g], bd);
            }
            #pragma unroll
            for (int mi = 0; mi < 2; mi++)
                #pragma unroll
                for (int ni = 0; ni < 8; ni++)
                    mma16816(acc[mi][ni], af[mi], &bf[ni >> 1][(ni & 1) * 2]);
        }
    }

    // epilogue
    int tg = lane >> 2, tc = lane & 3;
    if (outMode == 2) {
        float lsum = 0.f;
        #pragma unroll
        for (int mi = 0; mi < 2; mi++) {
            #pragma unroll
            for (int ni = 0; ni < 8; ni++) {
                int row = m0 + (wm << 5) + (mi << 4) + tg;
                int col = n0 + (wn << 6) + (ni << 3) + tc * 2;
                float* a4 = acc[mi][ni];
                #pragma unroll
                for (int h = 0; h < 2; h++) {
                    int r = row + h * 8;
                    int b = r >> 9, l = r & 511;
                    const float* xp = (l < LS_)
                        ? (xseq + ((long)b * LS_ + l) * D_ + col)
                        : (xlab + ((long)b * LL_ + (l - LS_)) * D_ + col);
                    float2 x2 = *(const float2*)xp;
                    float d0 = x2.x - a4[2 * h];
                    float d1 = x2.y - a4[2 * h + 1];
                    lsum += d0 * d0 + d1 * d1;
                }
            }
        }
        double bs = blockReduceSumD((double)lsum);
        if (tid == 0) atomicAdd(&g_acc[1], bs);
        return;
    }
    __nv_bfloat16* C;
    int nb = n0;
    if (outMode == 3) {
        int which = n0 >> 11;
        C = (which == 0) ? d_qb : ((which == 1) ? d_kb : d_vb);
        nb = n0 & 2047;
    } else {
        C = (__nv_bfloat16*)Cv;
    }
    #pragma unroll
    for (int mi = 0; mi < 2; mi++) {
        #pragma unroll
        for (int ni = 0; ni < 8; ni++) {
            int row = m0 + (wm << 5) + (mi << 4) + tg;
            int col = nb + (wn << 6) + (ni << 3) + tc * 2;
            float* a4 = acc[mi][ni];
            __nv_bfloat162 p0 = __floats2bfloat162_rn(a4[0] * alpha, a4[1] * alpha);
            __nv_bfloat162 p1 = __floats2bfloat162_rn(a4[2] * alpha, a4[3] * alpha);
            *(__nv_bfloat162*)(C + (long)row * ldc + col) = p0;
            *(__nv_bfloat162*)(C + (long)(row + 8) * ldc + col) = p1;
        }
    }
}

// ---------------- fully fused attention: S = QK^T -> softmax -> O = P V ----------------
#define ATTN_SMEM 229376

__global__ __launch_bounds__(256, 1) void attn_fused() {
    extern __shared__ __align__(16) char dsm[];
    uint32_t base = (uint32_t)__cvta_generic_to_shared(dsm);
    uint32_t pB = base;
    uint32_t kvB = base + 131072;
    uint32_t qB = base + 196608;

    int tid = threadIdx.x, lane = tid & 31, wid = tid >> 5;
    int z = blockIdx.y, m0 = blockIdx.x << 7;
    int b = z >> 4, h = z & 15;
    const __nv_bfloat16* Qg = d_qb + ((long)b * 512 + m0) * 2048 + h * 128;
    const __nv_bfloat16* Kg = d_kb + (long)b * 512 * 2048 + h * 128;
    const __nv_bfloat16* Vg = d_vb + (long)b * 512 * 2048 + h * 128;
    int wm = wid & 3, wn = wid >> 2;

    auto ld128 = [&](uint32_t dst, const __nv_bfloat16* src) {
        #pragma unroll
        for (int i = 0; i < 8; i++) {
            int id = i * 256 + tid;
            int r = id >> 4, u = id & 15;
            const void* g = src + (long)r * 2048 + u * 8;
            uint32_t d = dst + (uint32_t)(r * 256 + ((u ^ (r & 7)) << 4));
            asm volatile("cp.async.cg.shared.global [%0], [%1], 16;" :: "r"(d), "l"(g));
        }
    };

    ld128(qB, Qg);
    asm volatile("cp.async.commit_group;" ::: "memory");
    ld128(kvB, Kg);
    asm volatile("cp.async.commit_group;" ::: "memory");
    ld128(kvB + 32768, Kg + 128L * 2048);
    asm volatile("cp.async.commit_group;" ::: "memory");

    // ---- phase 1: S chunks -> P (bf16, scaled) ----
    for (int c = 0; c < 4; c++) {
        asm volatile("cp.async.wait_group 1;" ::: "memory");
        __syncthreads();
        uint32_t kvb = kvB + (c & 1) * 32768;
        float acc[2][8][4];
        #pragma unroll
        for (int i = 0; i < 2; i++)
            #pragma unroll
            for (int j = 0; j < 8; j++)
                #pragma unroll
                for (int q = 0; q < 4; q++) acc[i][j][q] = 0.f;
        #pragma unroll
        for (int k8 = 0; k8 < 8; k8++) {
            uint32_t af[2][4];
            #pragma unroll
            for (int mi = 0; mi < 2; mi++) {
                int row = (wm << 5) + (mi << 4) + (lane & 15);
                int u = (k8 << 1) + (lane >> 4);
                ldsm4(af[mi], qB + (uint32_t)(row * 256 + ((u ^ (row & 7)) << 4)));
            }
            uint32_t bf[4][4];
            #pragma unroll
            for (int g = 0; g < 4; g++) {
                int nrow = (wn << 6) + (g << 4) + ((lane >> 4) << 3) + (lane & 7);
                int u = (k8 << 1) + ((lane >> 3) & 1);
                ldsm4(bf[g], kvb + (uint32_t)(nrow * 256 + ((u ^ (nrow & 7)) << 4)));
            }
            #pragma unroll
            for (int mi = 0; mi < 2; mi++)
                #pragma unroll
                for (int ni = 0; ni < 8; ni++)
                    mma16816(acc[mi][ni], af[mi], &bf[ni >> 1][(ni & 1) * 2]);
        }
        int tg = lane >> 2, tc = lane & 3;
        #pragma unroll
        for (int mi = 0; mi < 2; mi++) {
            #pragma unroll
            for (int ni = 0; ni < 8; ni++) {
                int row = (wm << 5) + (mi << 4) + tg;
                int ub = (c << 4) + (wn << 3) + ni;
                float* a4 = acc[mi][ni];
                #pragma unroll
                for (int h2 = 0; h2 < 2; h2++) {
                    int r2 = row + h2 * 8;
                    uint32_t off = (uint32_t)(r2 * 1024 + ((ub ^ (r2 & 7)) << 4) + tc * 4);
                    *(__nv_bfloat162*)(dsm + off) = __floats2bfloat162_rn(
                        a4[2 * h2] * SCALE_, a4[2 * h2 + 1] * SCALE_);
                }
            }
        }
        __syncthreads();
        if (c < 2)       ld128(kvB + (c & 1) * 32768, Kg + (long)(c + 2) * 128 * 2048);
        else if (c == 2) ld128(kvB, Vg);
        else             ld128(kvB + 32768, Vg + 128L * 2048);
        asm volatile("cp.async.commit_group;" ::: "memory");
    }

    // ---- softmax in place on P ----
    for (int rr = 0; rr < 16; rr++) {
        int row = wid * 16 + rr;
        int x = row & 7;
        uint32_t a0 = (uint32_t)(row * 1024 + ((lane ^ x) << 4));
        uint32_t a1 = (uint32_t)(row * 1024 + (((lane + 32) ^ x) << 4));
        uint4 u0 = *(uint4*)(dsm + a0);
        uint4 u1 = *(uint4*)(dsm + a1);
        float v[16];
        const uint32_t* w0 = (const uint32_t*)&u0;
        const uint32_t* w1 = (const uint32_t*)&u1;
        #pragma unroll
        for (int j = 0; j < 4; j++) {
            __nv_bfloat162 h0 = *(__nv_bfloat162*)&w0[j];
            __nv_bfloat162 h1 = *(__nv_bfloat162*)&w1[j];
            v[2 * j]     = __bfloat162float(h0.x);
            v[2 * j + 1] = __bfloat162float(h0.y);
            v[8 + 2 * j] = __bfloat162float(h1.x);
            v[9 + 2 * j] = __bfloat162float(h1.y);
        }
        float m = v[0];
        #pragma unroll
        for (int j = 1; j < 16; j++) m = fmaxf(m, v[j]);
        #pragma unroll
        for (int o = 16; o > 0; o >>= 1) m = fmaxf(m, __shfl_xor_sync(0xffffffffu, m, o));
        float s = 0.f;
        #pragma unroll
        for (int j = 0; j < 16; j++) { v[j] = __expf(v[j] - m); s += v[j]; }
        #pragma unroll
        for (int o = 16; o > 0; o >>= 1) s += __shfl_xor_sync(0xffffffffu, s, o);
        float inv = 1.0f / s;
        uint32_t pk[8];
        #pragma unroll
        for (int j = 0; j < 4; j++) {
            __nv_bfloat162 pa = __floats2bfloat162_rn(v[2 * j] * inv, v[2 * j + 1] * inv);
            __nv_bfloat162 pb = __floats2bfloat162_rn(v[8 + 2 * j] * inv, v[9 + 2 * j] * inv);
            pk[j] = *(uint32_t*)&pa;
            pk[4 + j] = *(uint32_t*)&pb;
        }
        *(uint4*)(dsm + a0) = make_uint4(pk[0], pk[1], pk[2], pk[3]);
        *(uint4*)(dsm + a1) = make_uint4(pk[4], pk[5], pk[6], pk[7]);
    }

    // ---- phase 2: O = P @ V ----
    float acc[2][8][4];
    #pragma unroll
    for (int i = 0; i < 2; i++)
        #pragma unroll
        for (int j = 0; j < 8; j++)
            #pragma unroll
            for (int q = 0; q < 4; q++) acc[i][j][q] = 0.f;

    for (int c = 0; c < 4; c++) {
        if (c < 3) asm volatile("cp.async.wait_group 1;" ::: "memory");
        else       asm volatile("cp.async.wait_group 0;" ::: "memory");
        __syncthreads();
        uint32_t kvb = kvB + (c & 1) * 32768;
        #pragma unroll
        for (int k8 = 0; k8 < 8; k8++) {
            uint32_t af[2][4];
            #pragma unroll
            for (int mi = 0; mi < 2; mi++) {
                int row = (wm << 5) + (mi << 4) + (lane & 15);
                int u = ((c << 3) + k8) * 2 + (lane >> 4);
                ldsm4(af[mi], pB + (uint32_t)(row * 1024 + ((u ^ (row & 7)) << 4)));
            }
            uint32_t bf[4][4];
            #pragma unroll
            for (int g = 0; g < 4; g++) {
                int kl = (k8 << 4) + (lane & 7) + (((lane >> 3) & 1) << 3);
                int u = (wn << 3) + (g << 1) + (lane >> 4);
                ldsm4t(bf[g], kvb + (uint32_t)(kl * 256 + ((u ^ (kl & 7)) << 4)));
            }
            #pragma unroll
            for (int mi = 0; mi < 2; mi++)
                #pragma unroll
                for (int ni = 0; ni < 8; ni++)
                    mma16816(acc[mi][ni], af[mi], &bf[ni >> 1][(ni & 1) * 2]);
        }
        __syncthreads();
        if (c < 2) {
            ld128(kvB + (c & 1) * 32768, Vg + (long)(c + 2) * 128 * 2048);
            asm volatile("cp.async.commit_group;" ::: "memory");
        }
    }

    long cb = (long)b * 1048576 + (long)h * 128;
    int tg = lane >> 2, tc = lane & 3;
    #pragma unroll
    for (int mi = 0; mi < 2; mi++) {
        #pragma unroll
        for (int ni = 0; ni < 8; ni++) {
            int row = m0 + (wm << 5) + (mi << 4) + tg;
            int col = (wn << 6) + (ni << 3) + tc * 2;
            float* a4 = acc[mi][ni];
            __nv_bfloat162 p0 = __floats2bfloat162_rn(a4[0], a4[1]);
            __nv_bfloat162 p1 = __floats2bfloat162_rn(a4[2], a4[3]);
            *(__nv_bfloat162*)(d_ob + cb + (long)row * 2048 + col) = p0;
            *(__nv_bfloat162*)(d_ob + cb + (long)(row + 8) * 2048 + col) = p1;
        }
    }
}

__global__ void zero_acc_kernel() {
    if (threadIdx.x < 4) g_acc[threadIdx.x] = 0.0;
}

// x_t = sa*x_start + s1m*noise -> bf16; accumulate sum(x_start^2). 8 chunks/thread.
__global__ __launch_bounds__(256) void prep_kernel(
    const float* __restrict__ eseq, const float* __restrict__ elab,
    const float* __restrict__ noise, const float* __restrict__ sac,
    const float* __restrict__ s1mac, const int* __restrict__ tstep)
{
    double loc = 0.0;
    long base4 = (long)blockIdx.x * 2048 + threadIdx.x;
    #pragma unroll
    for (int i = 0; i < 8; i++) {
        long e = (base4 + i * 256) * 4;
        int d = (int)(e % D_);
        long bl = e / D_;
        int l = (int)(bl % L_);
        int b = (int)(bl / L_);
        float4 xs;
        if (l < LS_) xs = *(const float4*)(eseq + ((long)b * LS_ + l) * D_ + d);
        else         xs = *(const float4*)(elab + ((long)b * LL_ + (l - LS_)) * D_ + d);
        int t = tstep[b];
        float sa = sac[t], sm = s1mac[t];
        float4 nz = *(const float4*)(noise + e);
        __nv_bfloat162* ob = (__nv_bfloat162*)(d_xtb + e);
        ob[0] = __floats2bfloat162_rn(sa * xs.x + sm * nz.x, sa * xs.y + sm * nz.y);
        ob[1] = __floats2bfloat162_rn(sa * xs.z + sm * nz.z, sa * xs.w + sm * nz.w);
        loc += (double)xs.x * xs.x + (double)xs.y * xs.y +
               (double)xs.z * xs.z + (double)xs.w * xs.w;
    }
    double bs = blockReduceSumD(loc);
    if (threadIdx.x == 0) atomicAdd(&g_acc[0], bs);
}

// x_start[b,l,d] -> xT[d,b,l] (fp32, for contrast)
__global__ void transpose_kernel(const float* __restrict__ eseq,
                                 const float* __restrict__ elab)
{
    __shared__ float tile[32][33];
    int b = blockIdx.z;
    int d = blockIdx.x * 32 + threadIdx.x;
    int l = blockIdx.y * 32 + threadIdx.y;
    float v;
    if (l < LS_) v = eseq[((long)b * LS_ + l) * D_ + d];
    else         v = elab[((long)b * LL_ + (l - LS_)) * D_ + d];
    tile[threadIdx.y][threadIdx.x] = v;
    __syncthreads();
    int dw = blockIdx.x * 32 + threadIdx.y;
    int lw = blockIdx.y * 32 + threadIdx.x;
    d_xT[((long)dw * B_ + b) * L_ + lw] = tile[threadIdx.x][threadIdx.y];
}

// W[k,n] -> WT[n,k] bf16, 4 weights by blockIdx.z
__global__ void wt_kernel(const float* __restrict__ W0, const float* __restrict__ W1,
                          const float* __restrict__ W2, const float* __restrict__ W3)
{
    __shared__ float t[32][33];
    int zz = blockIdx.z;
    const float* W = (zz == 0) ? W0 : (zz == 1) ? W1 : (zz == 2) ? W2 : W3;
    int n = blockIdx.x * 32 + threadIdx.x;
    int k = blockIdx.y * 32 + threadIdx.y;
    t[threadIdx.y][threadIdx.x] = W[(long)k * 2048 + n];
    __syncthreads();
    int nn = blockIdx.x * 32 + threadIdx.y;
    int kk = blockIdx.y * 32 + threadIdx.x;
    d_wt[(long)zz * 4194304 + (long)nn * 2048 + kk] = __float2bfloat16(t[threadIdx.x][threadIdx.y]);
}

// ---------------- contrastive loss via tf32 mma ----------------
// grid (2048, 2): d = channel, mode 0 = (seq,label), 1 = (label,label).
// sim[32,32] = f1 @ f2^T (K=256) on tensor cores; norms + LSE in fp32.
// smem floats: f1s[32][260] | f2s[32][260] | lg[32][33] | inv1[32] | inv2[32] | bsum(double)[8]
#define CT_STR 260
#define CT_F2  8320      // float offset of f2s
#define CT_LG  16640     // float offset of lg
#define CT_I1  17696
#define CT_I2  17728
#define CT_BS  17760     // as double*, 8 entries (64B)
#define CT_SMEM ((17760 + 16) * 4)

__global__ __launch_bounds__(256) void contrast_mma() {
    extern __shared__ __align__(16) float smf[];
    float* f1s = smf;
    float* f2s = smf + CT_F2;
    float* lg  = smf + CT_LG;
    float* inv1 = smf + CT_I1;
    float* inv2 = smf + CT_I2;
    double* bsum = (double*)(smf + CT_BS);

    int d = blockIdx.x, mode = blockIdx.y;
    int tid = threadIdx.x, lane = tid & 31, wid = tid >> 5;
    const float* base = d_xT + (long)d * B_ * L_;
    long f1off = (mode == 0) ? 0 : LS_;

    // fill f1s, f2s (32 rows x 256 floats each = 2048 float4 each)
    #pragma unroll
    for (int i = 0; i < 8; i++) {
        int idx = i * 256 + tid;
        int r = idx >> 6, c = idx & 63;   // c = float4 index within row
        float4 v2 = *(const float4*)(base + (long)r * L_ + LS_ + c * 4);
        *(float4*)(f2s + r * CT_STR + c * 4) = v2;
        float4 v1 = *(const float4*)(base + (long)r * L_ + f1off + c * 4);
        *(float4*)(f1s + r * CT_STR + c * 4) = v1;
    }
    __syncthreads();

    // norms: thread t -> row t>>3, segment t&7 (8 float4 each)
    {
        int r = tid >> 3, seg = tid & 7;
        const float4* a = (const float4*)(f1s + r * CT_STR) + seg * 8;
        const float4* b = (const float4*)(f2s + r * CT_STR) + seg * 8;
        float s1 = 0.f, s2 = 0.f;
        #pragma unroll
        for (int j = 0; j < 8; j++) {
            float4 x = a[j], y = b[j];
            s1 += x.x * x.x + x.y * x.y + x.z * x.z + x.w * x.w;
            s2 += y.x * y.x + y.y * y.y + y.z * y.z + y.w * y.w;
        }
        #pragma unroll
        for (int o = 4; o > 0; o >>= 1) {
            s1 += __shfl_xor_sync(0xffffffffu, s1, o);
            s2 += __shfl_xor_sync(0xffffffffu, s2, o);
        }
        if (seg == 0) { inv1[r] = rsqrtf(s1); inv2[r] = rsqrtf(s2); }
    }
    __syncthreads();

    // sim via tf32 mma: warps 2(M) x 4(N), each 16x8 tile, K=256 in k8 steps
    {
        int mw = wid & 1, nw = wid >> 1;
        int g = lane >> 2, tig = lane & 3;
        int ar0 = mw * 16 + g, ar1 = ar0 + 8;
        int bn = nw * 8 + g;
        const float* a0p = f1s + ar0 * CT_STR + tig;
        const float* a1p = f1s + ar1 * CT_STR + tig;
        const float* bp  = f2s + bn * CT_STR + tig;
        float c0 = 0.f, c1 = 0.f, c2 = 0.f, c3 = 0.f;
        #pragma unroll 4
        for (int k8 = 0; k8 < 256; k8 += 8) {
            uint32_t a0 = f2tf32(a0p[k8]);
            uint32_t a1 = f2tf32(a1p[k8]);
            uint32_t a2 = f2tf32(a0p[k8 + 4]);
            uint32_t a3 = f2tf32(a1p[k8 + 4]);
            uint32_t b0 = f2tf32(bp[k8]);
            uint32_t b1 = f2tf32(bp[k8 + 4]);
            asm volatile(
                "mma.sync.aligned.m16n8k8.row.col.f32.tf32.tf32.f32 "
                "{%0,%1,%2,%3}, {%4,%5,%6,%7}, {%8,%9}, {%0,%1,%2,%3};"
                : "+f"(c0), "+f"(c1), "+f"(c2), "+f"(c3)
                : "r"(a0), "r"(a1), "r"(a2), "r"(a3), "r"(b0), "r"(b1));
        }
        int col0 = nw * 8 + 2 * tig, col1 = col0 + 1;
        float sA0 = inv1[ar0] * (1.0f / TAU_);
        float sA1 = inv1[ar1] * (1.0f / TAU_);
        lg[ar0 * 33 + col0] = c0 * sA0 * inv2[col0];
        lg[ar0 * 33 + col1] = c1 * sA0 * inv2[col1];
        lg[ar1 * 33 + col0] = c2 * sA1 * inv2[col0];
        lg[ar1 * 33 + col1] = c3 * sA1 * inv2[col1];
    }
    __syncthreads();

    // LSE: warp w handles rows 4w..4w+3
    double wsum = 0.0;
    #pragma unroll
    for (int rr = 0; rr < 4; rr++) {
        int row = wid * 4 + rr;
        float v = lg[row * 33 + lane];
        float mx = v;
        #pragma unroll
        for (int o = 16; o > 0; o >>= 1) mx = fmaxf(mx, __shfl_xor_sync(0xffffffffu, mx, o));
        float ex = __expf(v - mx);
        #pragma unroll
        for (int o = 16; o > 0; o >>= 1) ex += __shfl_xor_sync(0xffffffffu, ex, o);
        if (lane == 0) wsum += (double)(mx + __logf(ex) - lg[row * 33 + row]);
    }
    if (lane == 0) bsum[wid] = wsum;
    __syncthreads();
    if (tid == 0) {
        double t = 0.0;
        #pragma unroll
        for (int w = 0; w < 8; w++) t += bsum[w];
        atomicAdd(&g_acc[2 + mode], t);
    }
}

__global__ void finalize_kernel(const float* __restrict__ sac, float* __restrict__ out) {
    double inv = 1.0 / (double)NEL;
    double saT = (double)sac[T_ - 1];
    double mse = g_acc[1] * inv;
    double tT  = saT * saT * g_acc[0] * inv;
    double con = (g_acc[2] + g_acc[3]) / (2048.0 * 32.0);
    out[0] = (float)(mse + tT + con);
}

// ---------------- launch ----------------
extern "C" void kernel_launch(void* const* d_in, const int* in_sizes, int n_in,
                              void* d_out, int out_size)
{
    const float* eseq  = (const float*)d_in[0];
    const float* elab  = (const float*)d_in[1];
    const float* noise = (const float*)d_in[2];
    const float* sac   = (const float*)d_in[3];
    const float* s1m   = (const float*)d_in[4];
    const float* Wq    = (const float*)d_in[5];
    const float* Wk    = (const float*)d_in[6];
    const float* Wv    = (const float*)d_in[7];
    const float* Wo    = (const float*)d_in[8];
    const int*   ts    = (const int*)d_in[9];
    float* out = (float*)d_out;

    __nv_bfloat16 *xtb, *wt, *ob;
    cudaGetSymbolAddress((void**)&xtb, d_xtb);
    cudaGetSymbolAddress((void**)&wt,  d_wt);
    cudaGetSymbolAddress((void**)&ob,  d_ob);

    cudaFuncSetAttribute((const void*)mma_gemm,
                         cudaFuncAttributeMaxDynamicSharedMemorySize, SMEM_G);
    cudaFuncSetAttribute((const void*)attn_fused,
                         cudaFuncAttributeMaxDynamicSharedMemorySize, ATTN_SMEM);
    cudaFuncSetAttribute((const void*)contrast_mma,
                         cudaFuncAttributeMaxDynamicSharedMemorySize, CT_SMEM);

    static cudaStream_t s2 = nullptr;
    static cudaEvent_t eF = nullptr, eW = nullptr, eJ = nullptr;
    if (s2 == nullptr) {
        cudaStreamCreate(&s2);
        cudaEventCreateWithFlags(&eF, cudaEventDisableTiming);
        cudaEventCreateWithFlags(&eW, cudaEventDisableTiming);
        cudaEventCreateWithFlags(&eJ, cudaEventDisableTiming);
    }

    zero_acc_kernel<<<1, 32>>>();

    // fork: weight transpose + x_start transpose + contrast on side stream
    cudaEventRecord(eF, 0);
    cudaStreamWaitEvent(s2, eF, 0);
    wt_kernel<<<dim3(64, 64, 4), dim3(32, 32), 0, s2>>>(Wq, Wk, Wv, Wo);
    cudaEventRecord(eW, s2);
    transpose_kernel<<<dim3(64, 16, 32), dim3(32, 32), 0, s2>>>(eseq, elab);
    contrast_mma<<<dim3(2048, 2), 256, CT_SMEM, s2>>>();
    cudaEventRecord(eJ, s2);

    // main chain
    prep_kernel<<<4096, 256>>>(eseq, elab, noise, sac, s1m, ts);
    cudaStreamWaitEvent(0, eW, 0);

    // fused Q/K/V projection: N = 6144 over [WqT; WkT; WvT]
    mma_gemm<<<dim3(48, 128, 1), 256, SMEM_G>>>(
        xtb, 2048, wt, 2048, nullptr, 2048, 2048, 1.0f, 3, nullptr, nullptr);

    // fused attention: S = QK^T, softmax, O = PV
    attn_fused<<<dim3(4, 512), 256, ATTN_SMEM>>>();

    // model_output = O @ Wo^T, fused MSE vs x_start (no store)
    mma_gemm<<<dim3(16, 128, 1), 256, SMEM_G>>>(
        ob, 2048, wt + 3L * 4194304, 2048, nullptr, 2048, 2048, 1.0f, 2, eseq, elab);

    // join side chain, then finalize
    cudaStreamWaitEvent(0, eJ, 0);
    finalize_kernel<<<1, 1>>>(sac, out);
}

// round 15
// speedup vs baseline: 1.0910x; 1.0220x over previous
#include <cuda_runtime.h>
#include <cuda_bf16.h>
#include <cstdint>

// ---------------- problem constants ----------------
#define B_   32
#define LS_  256
#define LL_  256
#define L_   512
#define D_   2048
#define H_   16
#define DH_  128
#define T_   1000
#define TAU_ 0.07f
#define SCALE_ 0.08838834764831845f

#define NEL  33554432L   // B*L*D

// ---------------- scratch buffers (static, no allocation) ----------------
__device__ __nv_bfloat16 d_xtb[NEL];            // x_t bf16 [B,L,D]
__device__ __nv_bfloat16 d_wt[4L*2048*2048];    // WqT,WkT,WvT,WoT bf16 [N,K]
__device__ __nv_bfloat16 d_qb[NEL];             // Q bf16
__device__ __nv_bfloat16 d_kb[NEL];             // K bf16
__device__ __nv_bfloat16 d_vb[NEL];             // V bf16
__device__ __nv_bfloat16 d_ob[NEL];             // attn out bf16
__device__ float d_xT[NEL];                     // x_start^T [D,B,L] fp32
__device__ double g_acc[4];

// ---------------- reduction helper ----------------
__device__ __forceinline__ double blockReduceSumD(double v) {
    __shared__ double sh[8];
    #pragma unroll
    for (int o = 16; o > 0; o >>= 1) v += __shfl_down_sync(0xffffffffu, v, o);
    int lane = threadIdx.x & 31, w = threadIdx.x >> 5;
    if (lane == 0) sh[w] = v;
    __syncthreads();
    if (w == 0) {
        v = (lane < (int)(blockDim.x >> 5)) ? sh[lane] : 0.0;
        #pragma unroll
        for (int o = 4; o > 0; o >>= 1) v += __shfl_down_sync(0xffffffffu, v, o);
    }
    return v;
}

// ---------------- mma helpers ----------------
__device__ __forceinline__ void mma16816(float* c, const uint32_t* a, const uint32_t* b) {
    asm volatile(
        "mma.sync.aligned.m16n8k16.row.col.f32.bf16.bf16.f32 "
        "{%0,%1,%2,%3}, {%4,%5,%6,%7}, {%8,%9}, {%0,%1,%2,%3};"
        : "+f"(c[0]), "+f"(c[1]), "+f"(c[2]), "+f"(c[3])
        : "r"(a[0]), "r"(a[1]), "r"(a[2]), "r"(a[3]), "r"(b[0]), "r"(b[1]));
}
__device__ __forceinline__ void ldsm4(uint32_t* f, uint32_t addr) {
    asm volatile("ldmatrix.sync.aligned.m8n8.x4.shared.b16 {%0,%1,%2,%3}, [%4];"
                 : "=r"(f[0]), "=r"(f[1]), "=r"(f[2]), "=r"(f[3]) : "r"(addr));
}
__device__ __forceinline__ void ldsm4t(uint32_t* f, uint32_t addr) {
    asm volatile("ldmatrix.sync.aligned.m8n8.x4.trans.shared.b16 {%0,%1,%2,%3}, [%4];"
                 : "=r"(f[0]), "=r"(f[1]), "=r"(f[2]), "=r"(f[3]) : "r"(addr));
}
__device__ __forceinline__ uint32_t f2tf32(float x) {
    uint32_t r;
    asm("cvt.rna.tf32.f32 %0, %1;" : "=r"(r) : "f"(x));
    return r;
}
__device__ __forceinline__ void mmatf(float* c, uint32_t a0, uint32_t a1,
                                      uint32_t a2, uint32_t a3,
                                      uint32_t b0, uint32_t b1) {
    asm volatile(
        "mma.sync.aligned.m16n8k8.row.col.f32.tf32.tf32.f32 "
        "{%0,%1,%2,%3}, {%4,%5,%6,%7}, {%8,%9}, {%0,%1,%2,%3};"
        : "+f"(c[0]), "+f"(c[1]), "+f"(c[2]), "+f"(c[3])
        : "r"(a0), "r"(a1), "r"(a2), "r"(a3), "r"(b0), "r"(b1));
}

// ---------------- batched bf16 MMA GEMM (R7/R11-proven config) ----------------
// C = alpha * A[M,K] @ B[N,K]^T. 128x128 CTA tile, 32x64 warp tile, BK=64,
// 3-stage cp.async, one sync per k-step, 256 threads (8 warps), 2 CTA/SM.
// outMode: 1=bf16 store, 2=fused MSE vs concat(eseq,elab), 3=QKV split.
#define SROWK 144   // 128B data + 16B pad
#define G_STAGES 3
#define G_STAGE_BYTES ((128 + 128) * SROWK)
#define SMEM_G (G_STAGES * G_STAGE_BYTES)   // 110592

__global__ __launch_bounds__(256, 2) void mma_gemm(
    const __nv_bfloat16* __restrict__ A, int lda,
    const __nv_bfloat16* __restrict__ Bm, int ldb,
    void* __restrict__ Cv, int ldc,
    int K, float alpha, int outMode,
    const float* __restrict__ xseq, const float* __restrict__ xlab)
{
    extern __shared__ __align__(16) char dsm[];
    uint32_t sbase = (uint32_t)__cvta_generic_to_shared(dsm);

    int tid = threadIdx.x, lane = tid & 31, wid = tid >> 5;
    int m0 = blockIdx.y << 7, n0 = blockIdx.x << 7;
    int wm = wid & 3, wn = wid >> 2;   // 4 M-warps x 2 N-warps

    const __nv_bfloat16* Ag = A + (long)m0 * lda;
    const __nv_bfloat16* Bg = Bm + (long)n0 * ldb;

    float acc[2][8][4];
    #pragma unroll
    for (int i = 0; i < 2; i++)
        #pragma unroll
        for (int j = 0; j < 8; j++)
            #pragma unroll
            for (int q = 0; q < 4; q++) acc[i][j][q] = 0.f;

    auto load_tile = [&](int sidx, int buf) {
        const __nv_bfloat16* Ab = Ag + (long)sidx * 64;
        const __nv_bfloat16* Bb = Bg + (long)sidx * 64;
        uint32_t stA = sbase + buf * G_STAGE_BYTES;
        uint32_t stB = stA + 128 * SROWK;
        #pragma unroll
        for (int i = 0; i < 4; i++) {
            int ch = i * 256 + tid;
            int r = ch >> 3, c = ch & 7;
            uint32_t so = (uint32_t)(r * SROWK + c * 16);
            const void* ga = Ab + (long)r * lda + c * 8;
            asm volatile("cp.async.cg.shared.global [%0], [%1], 16;" :: "r"(stA + so), "l"(ga));
            const void* gb = Bb + (long)r * ldb + c * 8;
            asm volatile("cp.async.cg.shared.global [%0], [%1], 16;" :: "r"(stB + so), "l"(gb));
        }
    };

    int nt = K >> 6;
    #pragma unroll
    for (int i = 0; i < G_STAGES - 1; i++) {
        if (i < nt) load_tile(i, i);
        asm volatile("cp.async.commit_group;" ::: "memory");
    }

    for (int s = 0; s < nt; s++) {
        asm volatile("cp.async.wait_group %0;" :: "n"(G_STAGES - 2) : "memory");
        __syncthreads();
        int pf = s + G_STAGES - 1;
        if (pf < nt) load_tile(pf, pf % G_STAGES);
        asm volatile("cp.async.commit_group;" ::: "memory");

        uint32_t baseA = sbase + (s % G_STAGES) * G_STAGE_BYTES;
        uint32_t baseB = baseA + 128 * SROWK;
        #pragma unroll
        for (int kk = 0; kk < 4; kk++) {
            uint32_t af[2][4];
            #pragma unroll
            for (int mi = 0; mi < 2; mi++) {
                int row = (wm << 5) + (mi << 4) + (lane & 15);
                uint32_t ad = baseA + (uint32_t)(row * SROWK + (kk << 5) + ((lane >> 4) << 4));
                ldsm4(af[mi], ad);
            }
            uint32_t bf[4][4];
            #pragma unroll
            for (int g = 0; g < 4; g++) {
                int nrow = (wn << 6) + (g << 4) + ((lane >> 4) << 3) + (lane & 7);
                uint32_t bd = baseB + (uint32_t)(nrow * SROWK + (kk << 5) + (((lane >> 3) & 1) << 4));
                ldsm4(bf[g], bd);
            }
            #pragma unroll
            for (int mi = 0; mi < 2; mi++)
                #pragma unroll
                for (int ni = 0; ni < 8; ni++)
                    mma16816(acc[mi][ni], af[mi], &bf[ni >> 1][(ni & 1) * 2]);
        }
    }

    // epilogue
    int tg = lane >> 2, tc = lane & 3;
    if (outMode == 2) {
        float lsum = 0.f;
        #pragma unroll
        for (int mi = 0; mi < 2; mi++) {
            #pragma unroll
            for (int ni = 0; ni < 8; ni++) {
                int row = m0 + (wm << 5) + (mi << 4) + tg;
                int col = n0 + (wn << 6) + (ni << 3) + tc * 2;
                float* a4 = acc[mi][ni];
                #pragma unroll
                for (int h = 0; h < 2; h++) {
                    int r = row + h * 8;
                    int b = r >> 9, l = r & 511;
                    const float* xp = (l < LS_)
                        ? (xseq + ((long)b * LS_ + l) * D_ + col)
                        : (xlab + ((long)b * LL_ + (l - LS_)) * D_ + col);
                    float2 x2 = *(const float2*)xp;
                    float d0 = x2.x - a4[2 * h];
                    float d1 = x2.y - a4[2 * h + 1];
                    lsum += d0 * d0 + d1 * d1;
                }
            }
        }
        double bs = blockReduceSumD((double)lsum);
        if (tid == 0) atomicAdd(&g_acc[1], bs);
        return;
    }
    __nv_bfloat16* C;
    int nb = n0;
    if (outMode == 3) {
        int which = n0 >> 11;
        C = (which == 0) ? d_qb : ((which == 1) ? d_kb : d_vb);
        nb = n0 & 2047;
    } else {
        C = (__nv_bfloat16*)Cv;
    }
    #pragma unroll
    for (int mi = 0; mi < 2; mi++) {
        #pragma unroll
        for (int ni = 0; ni < 8; ni++) {
            int row = m0 + (wm << 5) + (mi << 4) + tg;
            int col = nb + (wn << 6) + (ni << 3) + tc * 2;
            float* a4 = acc[mi][ni];
            __nv_bfloat162 p0 = __floats2bfloat162_rn(a4[0] * alpha, a4[1] * alpha);
            __nv_bfloat162 p1 = __floats2bfloat162_rn(a4[2] * alpha, a4[3] * alpha);
            *(__nv_bfloat162*)(C + (long)row * ldc + col) = p0;
            *(__nv_bfloat162*)(C + (long)(row + 8) * ldc + col) = p1;
        }
    }
}

// ---------------- fully fused attention: S = QK^T -> softmax -> O = P V ----------------
#define ATTN_SMEM 229376

__global__ __launch_bounds__(256, 1) void attn_fused() {
    extern __shared__ __align__(16) char dsm[];
    uint32_t base = (uint32_t)__cvta_generic_to_shared(dsm);
    uint32_t pB = base;
    uint32_t kvB = base + 131072;
    uint32_t qB = base + 196608;

    int tid = threadIdx.x, lane = tid & 31, wid = tid >> 5;
    int z = blockIdx.y, m0 = blockIdx.x << 7;
    int b = z >> 4, h = z & 15;
    const __nv_bfloat16* Qg = d_qb + ((long)b * 512 + m0) * 2048 + h * 128;
    const __nv_bfloat16* Kg = d_kb + (long)b * 512 * 2048 + h * 128;
    const __nv_bfloat16* Vg = d_vb + (long)b * 512 * 2048 + h * 128;
    int wm = wid & 3, wn = wid >> 2;

    auto ld128 = [&](uint32_t dst, const __nv_bfloat16* src) {
        #pragma unroll
        for (int i = 0; i < 8; i++) {
            int id = i * 256 + tid;
            int r = id >> 4, u = id & 15;
            const void* g = src + (long)r * 2048 + u * 8;
            uint32_t d = dst + (uint32_t)(r * 256 + ((u ^ (r & 7)) << 4));
            asm volatile("cp.async.cg.shared.global [%0], [%1], 16;" :: "r"(d), "l"(g));
        }
    };

    ld128(qB, Qg);
    asm volatile("cp.async.commit_group;" ::: "memory");
    ld128(kvB, Kg);
    asm volatile("cp.async.commit_group;" ::: "memory");
    ld128(kvB + 32768, Kg + 128L * 2048);
    asm volatile("cp.async.commit_group;" ::: "memory");

    // ---- phase 1: S chunks -> P (bf16, scaled) ----
    for (int c = 0; c < 4; c++) {
        asm volatile("cp.async.wait_group 1;" ::: "memory");
        __syncthreads();
        uint32_t kvb = kvB + (c & 1) * 32768;
        float acc[2][8][4];
        #pragma unroll
        for (int i = 0; i < 2; i++)
            #pragma unroll
            for (int j = 0; j < 8; j++)
                #pragma unroll
                for (int q = 0; q < 4; q++) acc[i][j][q] = 0.f;
        #pragma unroll
        for (int k8 = 0; k8 < 8; k8++) {
            uint32_t af[2][4];
            #pragma unroll
            for (int mi = 0; mi < 2; mi++) {
                int row = (wm << 5) + (mi << 4) + (lane & 15);
                int u = (k8 << 1) + (lane >> 4);
                ldsm4(af[mi], qB + (uint32_t)(row * 256 + ((u ^ (row & 7)) << 4)));
            }
            uint32_t bf[4][4];
            #pragma unroll
            for (int g = 0; g < 4; g++) {
                int nrow = (wn << 6) + (g << 4) + ((lane >> 4) << 3) + (lane & 7);
                int u = (k8 << 1) + ((lane >> 3) & 1);
                ldsm4(bf[g], kvb + (uint32_t)(nrow * 256 + ((u ^ (nrow & 7)) << 4)));
            }
            #pragma unroll
            for (int mi = 0; mi < 2; mi++)
                #pragma unroll
                for (int ni = 0; ni < 8; ni++)
                    mma16816(acc[mi][ni], af[mi], &bf[ni >> 1][(ni & 1) * 2]);
        }
        int tg = lane >> 2, tc = lane & 3;
        #pragma unroll
        for (int mi = 0; mi < 2; mi++) {
            #pragma unroll
            for (int ni = 0; ni < 8; ni++) {
                int row = (wm << 5) + (mi << 4) + tg;
                int ub = (c << 4) + (wn << 3) + ni;
                float* a4 = acc[mi][ni];
                #pragma unroll
                for (int h2 = 0; h2 < 2; h2++) {
                    int r2 = row + h2 * 8;
                    uint32_t off = (uint32_t)(r2 * 1024 + ((ub ^ (r2 & 7)) << 4) + tc * 4);
                    *(__nv_bfloat162*)(dsm + off) = __floats2bfloat162_rn(
                        a4[2 * h2] * SCALE_, a4[2 * h2 + 1] * SCALE_);
                }
            }
        }
        __syncthreads();
        if (c < 2)       ld128(kvB + (c & 1) * 32768, Kg + (long)(c + 2) * 128 * 2048);
        else if (c == 2) ld128(kvB, Vg);
        else             ld128(kvB + 32768, Vg + 128L * 2048);
        asm volatile("cp.async.commit_group;" ::: "memory");
    }

    // ---- softmax in place on P ----
    for (int rr = 0; rr < 16; rr++) {
        int row = wid * 16 + rr;
        int x = row & 7;
        uint32_t a0 = (uint32_t)(row * 1024 + ((lane ^ x) << 4));
        uint32_t a1 = (uint32_t)(row * 1024 + (((lane + 32) ^ x) << 4));
        uint4 u0 = *(uint4*)(dsm + a0);
        uint4 u1 = *(uint4*)(dsm + a1);
        float v[16];
        const uint32_t* w0 = (const uint32_t*)&u0;
        const uint32_t* w1 = (const uint32_t*)&u1;
        #pragma unroll
        for (int j = 0; j < 4; j++) {
            __nv_bfloat162 h0 = *(__nv_bfloat162*)&w0[j];
            __nv_bfloat162 h1 = *(__nv_bfloat162*)&w1[j];
            v[2 * j]     = __bfloat162float(h0.x);
            v[2 * j + 1] = __bfloat162float(h0.y);
            v[8 + 2 * j] = __bfloat162float(h1.x);
            v[9 + 2 * j] = __bfloat162float(h1.y);
        }
        float m = v[0];
        #pragma unroll
        for (int j = 1; j < 16; j++) m = fmaxf(m, v[j]);
        #pragma unroll
        for (int o = 16; o > 0; o >>= 1) m = fmaxf(m, __shfl_xor_sync(0xffffffffu, m, o));
        float s = 0.f;
        #pragma unroll
        for (int j = 0; j < 16; j++) { v[j] = __expf(v[j] - m); s += v[j]; }
        #pragma unroll
        for (int o = 16; o > 0; o >>= 1) s += __shfl_xor_sync(0xffffffffu, s, o);
        float inv = 1.0f / s;
        uint32_t pk[8];
        #pragma unroll
        for (int j = 0; j < 4; j++) {
            __nv_bfloat162 pa = __floats2bfloat162_rn(v[2 * j] * inv, v[2 * j + 1] * inv);
            __nv_bfloat162 pb = __floats2bfloat162_rn(v[8 + 2 * j] * inv, v[9 + 2 * j] * inv);
            pk[j] = *(uint32_t*)&pa;
            pk[4 + j] = *(uint32_t*)&pb;
        }
        *(uint4*)(dsm + a0) = make_uint4(pk[0], pk[1], pk[2], pk[3]);
        *(uint4*)(dsm + a1) = make_uint4(pk[4], pk[5], pk[6], pk[7]);
    }

    // ---- phase 2: O = P @ V ----
    float acc[2][8][4];
    #pragma unroll
    for (int i = 0; i < 2; i++)
        #pragma unroll
        for (int j = 0; j < 8; j++)
            #pragma unroll
            for (int q = 0; q < 4; q++) acc[i][j][q] = 0.f;

    for (int c = 0; c < 4; c++) {
        if (c < 3) asm volatile("cp.async.wait_group 1;" ::: "memory");
        else       asm volatile("cp.async.wait_group 0;" ::: "memory");
        __syncthreads();
        uint32_t kvb = kvB + (c & 1) * 32768;
        #pragma unroll
        for (int k8 = 0; k8 < 8; k8++) {
            uint32_t af[2][4];
            #pragma unroll
            for (int mi = 0; mi < 2; mi++) {
                int row = (wm << 5) + (mi << 4) + (lane & 15);
                int u = ((c << 3) + k8) * 2 + (lane >> 4);
                ldsm4(af[mi], pB + (uint32_t)(row * 1024 + ((u ^ (row & 7)) << 4)));
            }
            uint32_t bf[4][4];
            #pragma unroll
            for (int g = 0; g < 4; g++) {
                int kl = (k8 << 4) + (lane & 7) + (((lane >> 3) & 1) << 3);
                int u = (wn << 3) + (g << 1) + (lane >> 4);
                ldsm4t(bf[g], kvb + (uint32_t)(kl * 256 + ((u ^ (kl & 7)) << 4)));
            }
            #pragma unroll
            for (int mi = 0; mi < 2; mi++)
                #pragma unroll
                for (int ni = 0; ni < 8; ni++)
                    mma16816(acc[mi][ni], af[mi], &bf[ni >> 1][(ni & 1) * 2]);
        }
        __syncthreads();
        if (c < 2) {
            ld128(kvB + (c & 1) * 32768, Vg + (long)(c + 2) * 128 * 2048);
            asm volatile("cp.async.commit_group;" ::: "memory");
        }
    }

    long cb = (long)b * 1048576 + (long)h * 128;
    int tg = lane >> 2, tc = lane & 3;
    #pragma unroll
    for (int mi = 0; mi < 2; mi++) {
        #pragma unroll
        for (int ni = 0; ni < 8; ni++) {
            int row = m0 + (wm << 5) + (mi << 4) + tg;
            int col = (wn << 6) + (ni << 3) + tc * 2;
            float* a4 = acc[mi][ni];
            __nv_bfloat162 p0 = __floats2bfloat162_rn(a4[0], a4[1]);
            __nv_bfloat162 p1 = __floats2bfloat162_rn(a4[2], a4[3]);
            *(__nv_bfloat162*)(d_ob + cb + (long)row * 2048 + col) = p0;
            *(__nv_bfloat162*)(d_ob + cb + (long)(row + 8) * 2048 + col) = p1;
        }
    }
}

__global__ void zero_acc_kernel() {
    if (threadIdx.x < 4) g_acc[threadIdx.x] = 0.0;
}

// x_t = sa*x_start + s1m*noise -> bf16; accumulate sum(x_start^2). 8 chunks/thread.
__global__ __launch_bounds__(256) void prep_kernel(
    const float* __restrict__ eseq, const float* __restrict__ elab,
    const float* __restrict__ noise, const float* __restrict__ sac,
    const float* __restrict__ s1mac, const int* __restrict__ tstep)
{
    double loc = 0.0;
    long base4 = (long)blockIdx.x * 2048 + threadIdx.x;
    #pragma unroll
    for (int i = 0; i < 8; i++) {
        long e = (base4 + i * 256) * 4;
        int d = (int)(e % D_);
        long bl = e / D_;
        int l = (int)(bl % L_);
        int b = (int)(bl / L_);
        float4 xs;
        if (l < LS_) xs = *(const float4*)(eseq + ((long)b * LS_ + l) * D_ + d);
        else         xs = *(const float4*)(elab + ((long)b * LL_ + (l - LS_)) * D_ + d);
        int t = tstep[b];
        float sa = sac[t], sm = s1mac[t];
        float4 nz = *(const float4*)(noise + e);
        __nv_bfloat162* ob = (__nv_bfloat162*)(d_xtb + e);
        ob[0] = __floats2bfloat162_rn(sa * xs.x + sm * nz.x, sa * xs.y + sm * nz.y);
        ob[1] = __floats2bfloat162_rn(sa * xs.z + sm * nz.z, sa * xs.w + sm * nz.w);
        loc += (double)xs.x * xs.x + (double)xs.y * xs.y +
               (double)xs.z * xs.z + (double)xs.w * xs.w;
    }
    double bs = blockReduceSumD(loc);
    if (threadIdx.x == 0) atomicAdd(&g_acc[0], bs);
}

// x_start[b,l,d] -> xT[d,b,l] (fp32, for contrast)
__global__ void transpose_kernel(const float* __restrict__ eseq,
                                 const float* __restrict__ elab)
{
    __shared__ float tile[32][33];
    int b = blockIdx.z;
    int d = blockIdx.x * 32 + threadIdx.x;
    int l = blockIdx.y * 32 + threadIdx.y;
    float v;
    if (l < LS_) v = eseq[((long)b * LS_ + l) * D_ + d];
    else         v = elab[((long)b * LL_ + (l - LS_)) * D_ + d];
    tile[threadIdx.y][threadIdx.x] = v;
    __syncthreads();
    int dw = blockIdx.x * 32 + threadIdx.y;
    int lw = blockIdx.y * 32 + threadIdx.x;
    d_xT[((long)dw * B_ + b) * L_ + lw] = tile[threadIdx.x][threadIdx.y];
}

// W[k,n] -> WT[n,k] bf16, 4 weights by blockIdx.z
__global__ void wt_kernel(const float* __restrict__ W0, const float* __restrict__ W1,
                          const float* __restrict__ W2, const float* __restrict__ W3)
{
    __shared__ float t[32][33];
    int zz = blockIdx.z;
    const float* W = (zz == 0) ? W0 : (zz == 1) ? W1 : (zz == 2) ? W2 : W3;
    int n = blockIdx.x * 32 + threadIdx.x;
    int k = blockIdx.y * 32 + threadIdx.y;
    t[threadIdx.y][threadIdx.x] = W[(long)k * 2048 + n];
    __syncthreads();
    int nn = blockIdx.x * 32 + threadIdx.y;
    int kk = blockIdx.y * 32 + threadIdx.x;
    d_wt[(long)zz * 4194304 + (long)nn * 2048 + kk] = __float2bfloat16(t[threadIdx.x][threadIdx.y]);
}

// ---------------- merged contrastive loss via tf32 mma ----------------
// grid (2048): d = channel. Computes BOTH modes per CTA with dual accumulators:
//   match: seq @ lab^T -> g_acc[2];  ctr: lab @ lab^T -> g_acc[3]
// smem floats: seq[32][260] | lab[32][260] | lgm[32][33] | lgc[32][33]
//              | invs[32] | invl[32] | bsum double[16]
#define CT_STR 260
#define CT_LAB 8320
#define CT_LGM 16640
#define CT_LGC 17696
#define CT_IS  18752
#define CT_IL  18784
#define CT_BS  18816
#define CT_SMEM ((18816 + 32) * 4)

__global__ __launch_bounds__(256) void contrast_mma() {
    extern __shared__ __align__(16) float smf[];
    float* seqs = smf;
    float* labs = smf + CT_LAB;
    float* lgm  = smf + CT_LGM;
    float* lgc  = smf + CT_LGC;
    float* invs = smf + CT_IS;
    float* invl = smf + CT_IL;
    double* bsum = (double*)(smf + CT_BS);

    int d = blockIdx.x;
    int tid = threadIdx.x, lane = tid & 31, wid = tid >> 5;
    const float* base = d_xT + (long)d * B_ * L_;

    // fill seq + lab tiles (32 rows x 256 floats each)
    #pragma unroll
    for (int i = 0; i < 8; i++) {
        int idx = i * 256 + tid;
        int r = idx >> 6, c = idx & 63;
        float4 vs = *(const float4*)(base + (long)r * L_ + c * 4);
        *(float4*)(seqs + r * CT_STR + c * 4) = vs;
        float4 vl = *(const float4*)(base + (long)r * L_ + LS_ + c * 4);
        *(float4*)(labs + r * CT_STR + c * 4) = vl;
    }
    __syncthreads();

    // norms: thread t -> row t>>3, segment t&7 (8 float4 each)
    {
        int r = tid >> 3, seg = tid & 7;
        const float4* a = (const float4*)(seqs + r * CT_STR) + seg * 8;
        const float4* b = (const float4*)(labs + r * CT_STR) + seg * 8;
        float s1 = 0.f, s2 = 0.f;
        #pragma unroll
        for (int j = 0; j < 8; j++) {
            float4 x = a[j], y = b[j];
            s1 += x.x * x.x + x.y * x.y + x.z * x.z + x.w * x.w;
            s2 += y.x * y.x + y.y * y.y + y.z * y.z + y.w * y.w;
        }
        #pragma unroll
        for (int o = 4; o > 0; o >>= 1) {
            s1 += __shfl_xor_sync(0xffffffffu, s1, o);
            s2 += __shfl_xor_sync(0xffffffffu, s2, o);
        }
        if (seg == 0) { invs[r] = rsqrtf(s1); invl[r] = rsqrtf(s2); }
    }
    __syncthreads();

    // dual tf32 mma: warps 2(M) x 4(N), each a 16x8 tile of BOTH gram matrices.
    // B fragment (lab) shared; two independent accumulator chains double ILP.
    {
        int mw = wid & 1, nw = wid >> 1;
        int g = lane >> 2, tig = lane & 3;
        int ar0 = mw * 16 + g, ar1 = ar0 + 8;
        int bn = nw * 8 + g;
        const float* s0 = seqs + ar0 * CT_STR + tig;
        const float* s1 = seqs + ar1 * CT_STR + tig;
        const float* l0 = labs + ar0 * CT_STR + tig;
        const float* l1 = labs + ar1 * CT_STR + tig;
        const float* bp = labs + bn * CT_STR + tig;
        float am[4] = {0.f, 0.f, 0.f, 0.f};
        float ac[4] = {0.f, 0.f, 0.f, 0.f};
        #pragma unroll 4
        for (int k8 = 0; k8 < 256; k8 += 8) {
            uint32_t b0 = f2tf32(bp[k8]);
            uint32_t b1 = f2tf32(bp[k8 + 4]);
            mmatf(am, f2tf32(s0[k8]), f2tf32(s1[k8]),
                      f2tf32(s0[k8 + 4]), f2tf32(s1[k8 + 4]), b0, b1);
            mmatf(ac, f2tf32(l0[k8]), f2tf32(l1[k8]),
                      f2tf32(l0[k8 + 4]), f2tf32(l1[k8 + 4]), b0, b1);
        }
        int col0 = nw * 8 + 2 * tig, col1 = col0 + 1;
        float c0s = invl[col0] * (1.0f / TAU_);
        float c1s = invl[col1] * (1.0f / TAU_);
        lgm[ar0 * 33 + col0] = am[0] * invs[ar0] * c0s;
        lgm[ar0 * 33 + col1] = am[1] * invs[ar0] * c1s;
        lgm[ar1 * 33 + col0] = am[2] * invs[ar1] * c0s;
        lgm[ar1 * 33 + col1] = am[3] * invs[ar1] * c1s;
        lgc[ar0 * 33 + col0] = ac[0] * invl[ar0] * c0s;
        lgc[ar0 * 33 + col1] = ac[1] * invl[ar0] * c1s;
        lgc[ar1 * 33 + col0] = ac[2] * invl[ar1] * c0s;
        lgc[ar1 * 33 + col1] = ac[3] * invl[ar1] * c1s;
    }
    __syncthreads();

    // LSE over both matrices: warp w -> rows 4w..4w+3
    double wm_ = 0.0, wc_ = 0.0;
    #pragma unroll
    for (int rr = 0; rr < 4; rr++) {
        int row = wid * 4 + rr;
        float vm = lgm[row * 33 + lane];
        float vc = lgc[row * 33 + lane];
        float mm = vm, mc = vc;
        #pragma unroll
        for (int o = 16; o > 0; o >>= 1) {
            mm = fmaxf(mm, __shfl_xor_sync(0xffffffffu, mm, o));
            mc = fmaxf(mc, __shfl_xor_sync(0xffffffffu, mc, o));
        }
        float em = __expf(vm - mm), ec = __expf(vc - mc);
        #pragma unroll
        for (int o = 16; o > 0; o >>= 1) {
            em += __shfl_xor_sync(0xffffffffu, em, o);
            ec += __shfl_xor_sync(0xffffffffu, ec, o);
        }
        if (lane == 0) {
            wm_ += (double)(mm + __logf(em) - lgm[row * 33 + row]);
            wc_ += (double)(mc + __logf(ec) - lgc[row * 33 + row]);
        }
    }
    if (lane == 0) { bsum[wid] = wm_; bsum[8 + wid] = wc_; }
    __syncthreads();
    if (tid == 0) {
        double tm = 0.0, tc2 = 0.0;
        #pragma unroll
        for (int w = 0; w < 8; w++) { tm += bsum[w]; tc2 += bsum[8 + w]; }
        atomicAdd(&g_acc[2], tm);
        atomicAdd(&g_acc[3], tc2);
    }
}

__global__ void finalize_kernel(const float* __restrict__ sac, float* __restrict__ out) {
    double inv = 1.0 / (double)NEL;
    double saT = (double)sac[T_ - 1];
    double mse = g_acc[1] * inv;
    double tT  = saT * saT * g_acc[0] * inv;
    double con = (g_acc[2] + g_acc[3]) / (2048.0 * 32.0);
    out[0] = (float)(mse + tT + con);
}

// ---------------- launch ----------------
extern "C" void kernel_launch(void* const* d_in, const int* in_sizes, int n_in,
                              void* d_out, int out_size)
{
    const float* eseq  = (const float*)d_in[0];
    const float* elab  = (const float*)d_in[1];
    const float* noise = (const float*)d_in[2];
    const float* sac   = (const float*)d_in[3];
    const float* s1m   = (const float*)d_in[4];
    const float* Wq    = (const float*)d_in[5];
    const float* Wk    = (const float*)d_in[6];
    const float* Wv    = (const float*)d_in[7];
    const float* Wo    = (const float*)d_in[8];
    const int*   ts    = (const int*)d_in[9];
    float* out = (float*)d_out;

    __nv_bfloat16 *xtb, *wt, *ob;
    cudaGetSymbolAddress((void**)&xtb, d_xtb);
    cudaGetSymbolAddress((void**)&wt,  d_wt);
    cudaGetSymbolAddress((void**)&ob,  d_ob);

    cudaFuncSetAttribute((const void*)mma_gemm,
                         cudaFuncAttributeMaxDynamicSharedMemorySize, SMEM_G);
    cudaFuncSetAttribute((const void*)attn_fused,
                         cudaFuncAttributeMaxDynamicSharedMemorySize, ATTN_SMEM);
    cudaFuncSetAttribute((const void*)contrast_mma,
                         cudaFuncAttributeMaxDynamicSharedMemorySize, CT_SMEM);

    static cudaStream_t s2 = nullptr;
    static cudaEvent_t eF = nullptr, eW = nullptr, eJ = nullptr;
    if (s2 == nullptr) {
        cudaStreamCreate(&s2);
        cudaEventCreateWithFlags(&eF, cudaEventDisableTiming);
        cudaEventCreateWithFlags(&eW, cudaEventDisableTiming);
        cudaEventCreateWithFlags(&eJ, cudaEventDisableTiming);
    }

    zero_acc_kernel<<<1, 32>>>();

    // fork: weight transpose + x_start transpose + contrast on side stream
    cudaEventRecord(eF, 0);
    cudaStreamWaitEvent(s2, eF, 0);
    wt_kernel<<<dim3(64, 64, 4), dim3(32, 32), 0, s2>>>(Wq, Wk, Wv, Wo);
    cudaEventRecord(eW, s2);
    transpose_kernel<<<dim3(64, 16, 32), dim3(32, 32), 0, s2>>>(eseq, elab);
    contrast_mma<<<dim3(2048), 256, CT_SMEM, s2>>>();
    cudaEventRecord(eJ, s2);

    // main chain
    prep_kernel<<<4096, 256>>>(eseq, elab, noise, sac, s1m, ts);
    cudaStreamWaitEvent(0, eW, 0);

    // fused Q/K/V projection: N = 6144 over [WqT; WkT; WvT]
    mma_gemm<<<dim3(48, 128, 1), 256, SMEM_G>>>(
        xtb, 2048, wt, 2048, nullptr, 2048, 2048, 1.0f, 3, nullptr, nullptr);

    // fused attention: S = QK^T, softmax, O = PV
    attn_fused<<<dim3(4, 512), 256, ATTN_SMEM>>>();

    // model_output = O @ Wo^T, fused MSE vs x_start (no store)
    mma_gemm<<<dim3(16, 128, 1), 256, SMEM_G>>>(
        ob, 2048, wt + 3L * 4194304, 2048, nullptr, 2048, 2048, 1.0f, 2, eseq, elab);

    // join side chain, then finalize
    cudaStreamWaitEvent(0, eJ, 0);
    finalize_kernel<<<1, 1>>>(sac, out);
}